// round 15
// baseline (speedup 1.0000x reference)
#include <cuda_runtime.h>
#include <cuda_bf16.h>
#include <math.h>
#include <stdint.h>

#define Bc 2
#define Sc 2048
#define Dc 2048
#define Hc 16
#define HDc 128
#define Lc 10

// Scratch (static device globals — allocation-free per harness rules)
__device__ float g_attn[Bc*Sc*Dc];
__device__ float g_ak[Lc*Dc];
__device__ float g_av[Lc*Dc];
__device__ float g_partial[2*32*Lc*Dc];
// bf16 split scratch
__device__ __nv_bfloat16 g_xh[Bc*Sc*Dc];   // x split; later attn split
__device__ __nv_bfloat16 g_xl[Bc*Sc*Dc];
__device__ __nv_bfloat16 g_wth[4*Dc*Dc];   // stacked W^T hi [wq|wk|wv|wo]
__device__ __nv_bfloat16 g_wtl[4*Dc*Dc];   // stacked W^T lo
__device__ __nv_bfloat16 g_qh[Bc*Sc*Dc];
__device__ __nv_bfloat16 g_ql[Bc*Sc*Dc];
__device__ __nv_bfloat16 g_kh[Bc*Sc*Dc];
__device__ __nv_bfloat16 g_kl[Bc*Sc*Dc];
__device__ __nv_bfloat16 g_vh[Bc*Sc*Dc];   // [B,S,H,HD] (same layout as K)
__device__ __nv_bfloat16 g_vl[Bc*Sc*Dc];

#define SCALE 0.08838834764831845f  // 1/sqrt(128)

// ---------------------------------------------------------------------------
// mma.sync + ldmatrix + cp.async helpers
// ---------------------------------------------------------------------------
#define MMA16816(c, a0, a1, a2, a3, b0, b1) \
    asm volatile( \
        "mma.sync.aligned.m16n8k16.row.col.f32.bf16.bf16.f32 " \
        "{%0,%1,%2,%3}, {%4,%5,%6,%7}, {%8,%9}, {%0,%1,%2,%3};" \
        : "+f"((c)[0]), "+f"((c)[1]), "+f"((c)[2]), "+f"((c)[3]) \
        : "r"(a0), "r"(a1), "r"(a2), "r"(a3), "r"(b0), "r"(b1))

#define LDSM4(r0, r1, r2, r3, addr) \
    asm volatile("ldmatrix.sync.aligned.m8n8.x4.shared.b16 {%0,%1,%2,%3}, [%4];" \
                 : "=r"(r0), "=r"(r1), "=r"(r2), "=r"(r3) : "r"(addr))

#define LDSM4T(r0, r1, r2, r3, addr) \
    asm volatile("ldmatrix.sync.aligned.m8n8.x4.trans.shared.b16 {%0,%1,%2,%3}, [%4];" \
                 : "=r"(r0), "=r"(r1), "=r"(r2), "=r"(r3) : "r"(addr))

__device__ __forceinline__ uint32_t smem_u32(const void* p) {
    uint32_t a;
    asm("{ .reg .u64 t; cvta.to.shared.u64 t, %1; cvt.u32.u64 %0, t; }"
        : "=r"(a) : "l"(p));
    return a;
}
#define CPA16(saddr, gptr) \
    asm volatile("cp.async.cg.shared.global [%0], [%1], 16;" \
                 :: "r"(saddr), "l"(gptr))
#define CPA_COMMIT() asm volatile("cp.async.commit_group;")
#define CPA_WAIT(n)  asm volatile("cp.async.wait_group %0;" :: "n"(n))

__device__ __forceinline__ __nv_bfloat162 bsplit_hi(float a, float b) {
    __nv_bfloat162 r;
    r.x = __float2bfloat16(a);
    r.y = __float2bfloat16(b);
    return r;
}
__device__ __forceinline__ __nv_bfloat162 bsplit_lo(float a, float b,
                                                    __nv_bfloat162 h) {
    __nv_bfloat162 r;
    r.x = __float2bfloat16(a - __bfloat162float(h.x));
    r.y = __float2bfloat16(b - __bfloat162float(h.y));
    return r;
}

// ---------------------------------------------------------------------------
// Elementwise fp32 -> bf16 hi/lo split (x only)
// ---------------------------------------------------------------------------
__global__ __launch_bounds__(256) void split_kernel(
    const float* __restrict__ x, __nv_bfloat16* __restrict__ h,
    __nv_bfloat16* __restrict__ l)
{
    int i = blockIdx.x * 256 + threadIdx.x;
    float4 v = ((const float4*)x)[i];
    __nv_bfloat162 h01 = bsplit_hi(v.x, v.y);
    __nv_bfloat162 h23 = bsplit_hi(v.z, v.w);
    ((__nv_bfloat162*)h)[i * 2 + 0] = h01;
    ((__nv_bfloat162*)h)[i * 2 + 1] = h23;
    ((__nv_bfloat162*)l)[i * 2 + 0] = bsplit_lo(v.x, v.y, h01);
    ((__nv_bfloat162*)l)[i * 2 + 1] = bsplit_lo(v.z, v.w, h23);
}

// ---------------------------------------------------------------------------
// Transpose + split, 4 weights in one launch (blockIdx.z selects).
// ---------------------------------------------------------------------------
__global__ __launch_bounds__(256) void wtrans4_kernel(
    const float* __restrict__ W0, const float* __restrict__ W1,
    const float* __restrict__ W2, const float* __restrict__ W3,
    __nv_bfloat16* __restrict__ Th, __nv_bfloat16* __restrict__ Tl)
{
    __shared__ float tile[64][33];
    const int z = blockIdx.z;
    const float* W = (z == 0) ? W0 : (z == 1) ? W1 : (z == 2) ? W2 : W3;
    __nv_bfloat16* Tho = Th + (size_t)z * Dc * Dc;
    __nv_bfloat16* Tlo = Tl + (size_t)z * Dc * Dc;
    const int k0 = blockIdx.x * 64, n0 = blockIdx.y * 32;
    const int t = threadIdx.x;
    const int r = t >> 5, c = t & 31;
    #pragma unroll
    for (int i = 0; i < 8; i++)
        tile[r + i * 8][c] = W[(size_t)(k0 + r + i * 8) * Dc + n0 + c];
    __syncthreads();
    #pragma unroll
    for (int i = 0; i < 4; i++) {
        int n = r * 4 + i;
        float v0 = tile[2 * c][n];
        float v1 = tile[2 * c + 1][n];
        __nv_bfloat162 hh = bsplit_hi(v0, v1);
        size_t o = ((size_t)(n0 + n) * Dc + k0) >> 1;
        ((__nv_bfloat162*)Tho)[o + c] = hh;
        ((__nv_bfloat162*)Tlo)[o + c] = bsplit_lo(v0, v1, hh);
    }
}

// ---------------------------------------------------------------------------
// bf16x3 tensor-core GEMM, BK=64, 3-stage cp.async + ldmatrix.
// ---------------------------------------------------------------------------
#define SROW2 72
#define STG2 36864                         // elems per stage (4 * 128 * 72)
#define GNST 3
#define GEMM_SMEM (GNST * STG2 * 2)        // 221184 bytes

__global__ __launch_bounds__(256, 1) void mma_gemm_kernel(
    const __nv_bfloat16* __restrict__ Ah, const __nv_bfloat16* __restrict__ Al,
    const __nv_bfloat16* __restrict__ BhT, const __nv_bfloat16* __restrict__ BlT,
    const float* __restrict__ fc, const float* __restrict__ fs,
    __nv_bfloat16* __restrict__ oQh, __nv_bfloat16* __restrict__ oQl,
    __nv_bfloat16* __restrict__ oKh, __nv_bfloat16* __restrict__ oKl,
    __nv_bfloat16* __restrict__ oVh, __nv_bfloat16* __restrict__ oVl,
    float* __restrict__ oC, int mode, int K)
{
    extern __shared__ __align__(16) __nv_bfloat16 dsm[];
    const uint32_t sb = smem_u32(dsm);

    const int t = threadIdx.x, lane = t & 31, wid = t >> 5;
    const int wm = wid & 1, wn = wid >> 1;
    const int bm = blockIdx.y * 128, bn = blockIdx.x * 128;
    const int gid = lane >> 2, tig = lane & 3;

    const int aoffE = (wm * 64 + (lane & 15)) * SROW2 + ((lane >> 4) & 1) * 8;
    const int boffE = (wn * 32 + ((lane >> 4) & 1) * 8 + (lane & 7)) * SROW2
                    + ((lane >> 3) & 1) * 8;

    float acc[4][4][4];
    #pragma unroll
    for (int a = 0; a < 4; a++)
        #pragma unroll
        for (int b = 0; b < 4; b++)
            #pragma unroll
            for (int cc = 0; cc < 4; cc++) acc[a][b][cc] = 0.f;

    const int nst = K >> 6;

    #define LOAD_STAGE2(stg, k0) do {                                       \
        uint32_t base = sb + (stg) * STG2 * 2;                              \
        _Pragma("unroll")                                                   \
        for (int jj = 0; jj < 4; jj++) {                                    \
            int u = t + jj * 256;                                           \
            int row = u >> 3, ch = (u & 7) * 8;                             \
            size_t ga = (size_t)(bm + row) * K + (k0) + ch;                 \
            size_t gb = (size_t)(bn + row) * K + (k0) + ch;                 \
            CPA16(base + (row * SROW2 + ch) * 2, &Ah[ga]);                  \
            CPA16(base + (9216 + row * SROW2 + ch) * 2, &Al[ga]);           \
            CPA16(base + (18432 + row * SROW2 + ch) * 2, &BhT[gb]);         \
            CPA16(base + (27648 + row * SROW2 + ch) * 2, &BlT[gb]);         \
        }                                                                   \
        CPA_COMMIT();                                                       \
    } while (0)

    LOAD_STAGE2(0, 0);
    LOAD_STAGE2(1, 64);

    for (int it = 0; it < nst; it++) {
        // prefetch stage it+2 (its buffer was fully consumed at iter it-1)
        if (it + 2 < nst) {
            LOAD_STAGE2((it + 2) % GNST, (it + 2) * 64);
            CPA_WAIT(2);
        } else if (it + 1 < nst) {
            CPA_WAIT(1);
        } else {
            CPA_WAIT(0);
        }
        __syncthreads();

        const uint32_t base = sb + (it % GNST) * STG2 * 2;

        #pragma unroll
        for (int ks = 0; ks < 4; ks++) {
            uint32_t ah[4][4], al[4][4];
            #pragma unroll
            for (int mt = 0; mt < 4; mt++) {
                uint32_t aaddr = base + (aoffE + mt * 16 * SROW2 + ks * 16) * 2;
                LDSM4(ah[mt][0], ah[mt][1], ah[mt][2], ah[mt][3], aaddr);
                LDSM4(al[mt][0], al[mt][1], al[mt][2], al[mt][3],
                      aaddr + 9216 * 2);
            }
            #pragma unroll
            for (int ntp = 0; ntp < 2; ntp++) {
                uint32_t baddr = base +
                    (18432 + boffE + ntp * 16 * SROW2 + ks * 16) * 2;
                uint32_t bh0, bh1, bh2, bh3, bl0, bl1, bl2, bl3;
                LDSM4(bh0, bh1, bh2, bh3, baddr);
                LDSM4(bl0, bl1, bl2, bl3, baddr + 9216 * 2);
                #pragma unroll
                for (int mt = 0; mt < 4; mt++) {
                    MMA16816(acc[mt][2 * ntp],     ah[mt][0], ah[mt][1], ah[mt][2], ah[mt][3], bh0, bh1);
                    MMA16816(acc[mt][2 * ntp + 1], ah[mt][0], ah[mt][1], ah[mt][2], ah[mt][3], bh2, bh3);
                    MMA16816(acc[mt][2 * ntp],     ah[mt][0], ah[mt][1], ah[mt][2], ah[mt][3], bl0, bl1);
                    MMA16816(acc[mt][2 * ntp + 1], ah[mt][0], ah[mt][1], ah[mt][2], ah[mt][3], bl2, bl3);
                    MMA16816(acc[mt][2 * ntp],     al[mt][0], al[mt][1], al[mt][2], al[mt][3], bh0, bh1);
                    MMA16816(acc[mt][2 * ntp + 1], al[mt][0], al[mt][1], al[mt][2], al[mt][3], bh2, bh3);
                }
            }
        }
        __syncthreads();
    }

    // ---- epilogue ----
    #pragma unroll
    for (int mt = 0; mt < 4; mt++) {
        int row = bm + wm * 64 + mt * 16 + gid;
        #pragma unroll
        for (int nt = 0; nt < 4; nt++) {
            int colg = bn + wn * 32 + nt * 8 + tig * 2;
            float a0 = acc[mt][nt][0], a1 = acc[mt][nt][1];
            float a2 = acc[mt][nt][2], a3 = acc[mt][nt][3];
            if (mode == 1) {
                *(float2*)&oC[(size_t)row * Dc + colg] = make_float2(a0, a1);
                *(float2*)&oC[(size_t)(row + 8) * Dc + colg] = make_float2(a2, a3);
            } else {
                int seg = colg >> 11;
                int d = colg & 2047;
                float r00 = a0, r01 = a1, r10 = a2, r11 = a3;
                if (seg < 2) {   // RoPE for Q and K
                    int s0 = row & 2047, s1 = (row + 8) & 2047;
                    int j = (d & 127) >> 1;
                    float c0 = fc[s0 * 64 + j], n0 = fs[s0 * 64 + j];
                    float c1 = fc[s1 * 64 + j], n1 = fs[s1 * 64 + j];
                    r00 = a0 * c0 - a1 * n0; r01 = a0 * n0 + a1 * c0;
                    r10 = a2 * c1 - a3 * n1; r11 = a2 * n1 + a3 * c1;
                }
                __nv_bfloat16* dH = (seg == 0) ? oQh : (seg == 1) ? oKh : oVh;
                __nv_bfloat16* dL = (seg == 0) ? oQl : (seg == 1) ? oKl : oVl;
                size_t o0 = ((size_t)row * Dc + d) >> 1;
                size_t o1 = ((size_t)(row + 8) * Dc + d) >> 1;
                __nv_bfloat162 h0 = bsplit_hi(r00, r01);
                __nv_bfloat162 h1 = bsplit_hi(r10, r11);
                ((__nv_bfloat162*)dH)[o0] = h0;
                ((__nv_bfloat162*)dH)[o1] = h1;
                ((__nv_bfloat162*)dL)[o0] = bsplit_lo(r00, r01, h0);
                ((__nv_bfloat162*)dL)[o1] = bsplit_lo(r10, r11, h1);
            }
        }
    }
}

// ---------------------------------------------------------------------------
// Flash attention (bf16x3), ldmatrix (+trans for V), 2-stage K/V pipeline.
// ---------------------------------------------------------------------------
#define FQS 136
#define FQ_ELEMS (2 * 128 * FQS)              // Qh+Ql
#define FKV_ELEMS (4 * 64 * FQS)              // Kh,Kl,Vh,Vl each 64x136
#define FLASH_SMEM ((FQ_ELEMS + 2 * FKV_ELEMS) * 2)   // 208896 bytes

__global__ __launch_bounds__(256, 1) void flash_mma_kernel()
{
    extern __shared__ __align__(16) __nv_bfloat16 fsm[];
    __nv_bfloat16* sQh = fsm;
    __nv_bfloat16* sQl = sQh + 128 * FQS;
    const uint32_t uQh = smem_u32(sQh), uQl = smem_u32(sQl);
    const uint32_t uS0 = uQh + FQ_ELEMS * 2;

    const int t = threadIdx.x, lane = t & 31, w = t >> 5;
    const int gid = lane >> 2, tig = lane & 3;
    const int qt = gridDim.x - 1 - blockIdx.x;   // longest first
    const int h = blockIdx.y, b = blockIdx.z;
    const int qbase = qt * 128;

    const int qaoffE = (w * 16 + (lane & 15)) * FQS + ((lane >> 4) & 1) * 8;
    const int kboffE = (((lane >> 4) & 1) * 8 + (lane & 7)) * FQS
                     + ((lane >> 3) & 1) * 8;
    const int vboffE = (lane & 15) * FQS + ((lane >> 4) & 1) * 8;

    #pragma unroll
    for (int i = 0; i < 8; i++) {
        int u = t + i * 256;
        int row = u >> 4, c8 = (u & 15) * 8;
        size_t g = ((size_t)(b * Sc + qbase + row)) * Dc + h * HDc + c8;
        *(uint4*)&sQh[row * FQS + c8] = *(const uint4*)&g_qh[g];
        *(uint4*)&sQl[row * FQS + c8] = *(const uint4*)&g_ql[g];
    }

    const int row0 = qbase + w * 16 + gid;
    const int row1 = row0 + 8;

    float m0 = -1e30f, m1 = -1e30f, l0 = 0.f, l1 = 0.f;
    float oacc[16][4];
    #pragma unroll
    for (int i = 0; i < 16; i++)
        #pragma unroll
        for (int j = 0; j < 4; j++) oacc[i][j] = 0.f;

    const int ntk = 2 * qt + 2;

    #define LOAD_KV(kt_) do {                                               \
        const uint32_t sb2 = uS0 + ((kt_) & 1) * FKV_ELEMS * 2;             \
        const int kb_ = (kt_) * 64;                                         \
        _Pragma("unroll")                                                   \
        for (int i = 0; i < 4; i++) {                                       \
            int u = t + i * 256;                                            \
            int krow = u >> 4, c8 = (u & 15) * 8;                           \
            size_t gk = ((size_t)(b * Sc + kb_ + krow)) * Dc + h * HDc + c8;\
            CPA16(sb2 + (krow * FQS + c8) * 2, &g_kh[gk]);                  \
            CPA16(sb2 + (8704 + krow * FQS + c8) * 2, &g_kl[gk]);           \
            CPA16(sb2 + (17408 + krow * FQS + c8) * 2, &g_vh[gk]);          \
            CPA16(sb2 + (26112 + krow * FQS + c8) * 2, &g_vl[gk]);          \
        }                                                                   \
        CPA_COMMIT();                                                       \
    } while (0)

    LOAD_KV(0);

    for (int kt = 0; kt < ntk; kt++) {
        const int kbase = kt * 64;
        if (kt + 1 < ntk) {
            LOAD_KV(kt + 1);
            CPA_WAIT(1);
        } else {
            CPA_WAIT(0);
        }
        __syncthreads();

        const uint32_t sb2 = uS0 + (kt & 1) * FKV_ELEMS * 2;
        const uint32_t uKh2 = sb2, uKl2 = sb2 + 8704 * 2;
        const uint32_t uVh2 = sb2 + 17408 * 2, uVl2 = sb2 + 26112 * 2;

        float sacc[8][4];
        #pragma unroll
        for (int nt = 0; nt < 8; nt++)
            #pragma unroll
            for (int j = 0; j < 4; j++) sacc[nt][j] = 0.f;

        #pragma unroll
        for (int kc = 0; kc < 8; kc++) {
            uint32_t ah0, ah1, ah2, ah3, al0, al1, al2, al3;
            LDSM4(ah0, ah1, ah2, ah3, uQh + (qaoffE + kc * 16) * 2);
            LDSM4(al0, al1, al2, al3, uQl + (qaoffE + kc * 16) * 2);
            #pragma unroll
            for (int ntp = 0; ntp < 4; ntp++) {
                uint32_t kaddr = (kboffE + ntp * 16 * FQS + kc * 16) * 2;
                uint32_t bh0, bh1, bh2, bh3, bl0, bl1, bl2, bl3;
                LDSM4(bh0, bh1, bh2, bh3, uKh2 + kaddr);
                LDSM4(bl0, bl1, bl2, bl3, uKl2 + kaddr);
                MMA16816(sacc[2 * ntp],     ah0, ah1, ah2, ah3, bh0, bh1);
                MMA16816(sacc[2 * ntp + 1], ah0, ah1, ah2, ah3, bh2, bh3);
                MMA16816(sacc[2 * ntp],     ah0, ah1, ah2, ah3, bl0, bl1);
                MMA16816(sacc[2 * ntp + 1], ah0, ah1, ah2, ah3, bl2, bl3);
                MMA16816(sacc[2 * ntp],     al0, al1, al2, al3, bh0, bh1);
                MMA16816(sacc[2 * ntp + 1], al0, al1, al2, al3, bh2, bh3);
            }
        }

        const bool need_mask = (kt >= 2 * qt);
        #pragma unroll
        for (int nt = 0; nt < 8; nt++) {
            int c0 = kbase + nt * 8 + 2 * tig;
            float v0 = sacc[nt][0] * SCALE;
            float v1 = sacc[nt][1] * SCALE;
            float v2 = sacc[nt][2] * SCALE;
            float v3 = sacc[nt][3] * SCALE;
            if (need_mask) {
                if (c0 > row0)     v0 -= 1e9f;
                if (c0 + 1 > row0) v1 -= 1e9f;
                if (c0 > row1)     v2 -= 1e9f;
                if (c0 + 1 > row1) v3 -= 1e9f;
            }
            sacc[nt][0] = v0; sacc[nt][1] = v1;
            sacc[nt][2] = v2; sacc[nt][3] = v3;
        }

        float mx0 = -1e30f, mx1 = -1e30f;
        #pragma unroll
        for (int nt = 0; nt < 8; nt++) {
            mx0 = fmaxf(mx0, fmaxf(sacc[nt][0], sacc[nt][1]));
            mx1 = fmaxf(mx1, fmaxf(sacc[nt][2], sacc[nt][3]));
        }
        mx0 = fmaxf(mx0, __shfl_xor_sync(0xffffffffu, mx0, 1));
        mx0 = fmaxf(mx0, __shfl_xor_sync(0xffffffffu, mx0, 2));
        mx1 = fmaxf(mx1, __shfl_xor_sync(0xffffffffu, mx1, 1));
        mx1 = fmaxf(mx1, __shfl_xor_sync(0xffffffffu, mx1, 2));
        float nm0 = fmaxf(m0, mx0), nm1 = fmaxf(m1, mx1);
        float corr0 = __expf(m0 - nm0), corr1 = __expf(m1 - nm1);
        m0 = nm0; m1 = nm1;

        float rs0 = 0.f, rs1 = 0.f;
        uint32_t ph01[8], ph23[8], pl01[8], pl23[8];
        #pragma unroll
        for (int nt = 0; nt < 8; nt++) {
            float e0 = __expf(sacc[nt][0] - nm0);
            float e1 = __expf(sacc[nt][1] - nm0);
            float e2 = __expf(sacc[nt][2] - nm1);
            float e3 = __expf(sacc[nt][3] - nm1);
            rs0 += e0 + e1; rs1 += e2 + e3;
            __nv_bfloat162 h01 = __floats2bfloat162_rn(e0, e1);
            __nv_bfloat162 h23 = __floats2bfloat162_rn(e2, e3);
            __nv_bfloat162 lo01 = __floats2bfloat162_rn(
                e0 - __bfloat162float(h01.x), e1 - __bfloat162float(h01.y));
            __nv_bfloat162 lo23 = __floats2bfloat162_rn(
                e2 - __bfloat162float(h23.x), e3 - __bfloat162float(h23.y));
            ph01[nt] = *(uint32_t*)&h01;
            ph23[nt] = *(uint32_t*)&h23;
            pl01[nt] = *(uint32_t*)&lo01;
            pl23[nt] = *(uint32_t*)&lo23;
        }
        rs0 += __shfl_xor_sync(0xffffffffu, rs0, 1);
        rs0 += __shfl_xor_sync(0xffffffffu, rs0, 2);
        rs1 += __shfl_xor_sync(0xffffffffu, rs1, 1);
        rs1 += __shfl_xor_sync(0xffffffffu, rs1, 2);
        l0 = l0 * corr0 + rs0;
        l1 = l1 * corr1 + rs1;

        #pragma unroll
        for (int nto = 0; nto < 16; nto++) {
            oacc[nto][0] *= corr0; oacc[nto][1] *= corr0;
            oacc[nto][2] *= corr1; oacc[nto][3] *= corr1;
        }

        // ---- O += P V (V fragments via ldmatrix.trans from [s][d]) ----
        #pragma unroll
        for (int j = 0; j < 4; j++) {
            uint32_t a0h = ph01[2 * j],     a1h = ph23[2 * j];
            uint32_t a2h = ph01[2 * j + 1], a3h = ph23[2 * j + 1];
            uint32_t a0l = pl01[2 * j],     a1l = pl23[2 * j];
            uint32_t a2l = pl01[2 * j + 1], a3l = pl23[2 * j + 1];
            #pragma unroll
            for (int ntp = 0; ntp < 4; ntp++) {
                uint32_t vaddr = (vboffE + j * 16 * FQS + ntp * 32) * 2;
                uint32_t vh0, vh1, vh2, vh3, vl0, vl1, vl2, vl3;
                LDSM4T(vh0, vh1, vh2, vh3, uVh2 + vaddr);
                LDSM4T(vl0, vl1, vl2, vl3, uVl2 + vaddr);
                MMA16816(oacc[4 * ntp],     a0h, a1h, a2h, a3h, vh0, vh1);
                MMA16816(oacc[4 * ntp + 1], a0h, a1h, a2h, a3h, vh2, vh3);
                MMA16816(oacc[4 * ntp],     a0h, a1h, a2h, a3h, vl0, vl1);
                MMA16816(oacc[4 * ntp + 1], a0h, a1h, a2h, a3h, vl2, vl3);
                MMA16816(oacc[4 * ntp],     a0l, a1l, a2l, a3l, vh0, vh1);
                MMA16816(oacc[4 * ntp + 1], a0l, a1l, a2l, a3l, vh2, vh3);

                uint32_t vaddr2 = (vboffE + j * 16 * FQS + ntp * 32 + 16) * 2;
                uint32_t wh0, wh1, wh2, wh3, wl0, wl1, wl2, wl3;
                LDSM4T(wh0, wh1, wh2, wh3, uVh2 + vaddr2);
                LDSM4T(wl0, wl1, wl2, wl3, uVl2 + vaddr2);
                MMA16816(oacc[4 * ntp + 2], a0h, a1h, a2h, a3h, wh0, wh1);
                MMA16816(oacc[4 * ntp + 3], a0h, a1h, a2h, a3h, wh2, wh3);
                MMA16816(oacc[4 * ntp + 2], a0h, a1h, a2h, a3h, wl0, wl1);
                MMA16816(oacc[4 * ntp + 3], a0h, a1h, a2h, a3h, wl2, wl3);
                MMA16816(oacc[4 * ntp + 2], a0l, a1l, a2l, a3l, wh0, wh1);
                MMA16816(oacc[4 * ntp + 3], a0l, a1l, a2l, a3l, wh2, wh3);
            }
        }
        __syncthreads();
    }

    // ---- epilogue: add adapter contribution, emit bf16 hi/lo split ----
    float i0 = 1.f / l0, i1 = 1.f / l1;
    #pragma unroll
    for (int nto = 0; nto < 16; nto++) {
        int col = h * HDc + nto * 8 + 2 * tig;
        size_t o0 = ((size_t)(b * Sc + row0)) * Dc + col;
        size_t o1 = ((size_t)(b * Sc + row1)) * Dc + col;
        float2 ad0 = *(const float2*)&g_attn[o0];
        float2 ad1 = *(const float2*)&g_attn[o1];
        float f00 = oacc[nto][0] * i0 + ad0.x;
        float f01 = oacc[nto][1] * i0 + ad0.y;
        float f10 = oacc[nto][2] * i1 + ad1.x;
        float f11 = oacc[nto][3] * i1 + ad1.y;
        __nv_bfloat162 h0 = bsplit_hi(f00, f01);
        __nv_bfloat162 h1 = bsplit_hi(f10, f11);
        ((__nv_bfloat162*)g_xh)[o0 >> 1] = h0;
        ((__nv_bfloat162*)g_xh)[o1 >> 1] = h1;
        ((__nv_bfloat162*)g_xl)[o0 >> 1] = bsplit_lo(f00, f01, h0);
        ((__nv_bfloat162*)g_xl)[o1 >> 1] = bsplit_lo(f10, f11, h1);
    }
}

// ---------------------------------------------------------------------------
// Adapter projection (both weights): grid (Dc/128, 32 k-splits, 2), 128 thr.
// ---------------------------------------------------------------------------
__global__ __launch_bounds__(128) void adapter_proj2_kernel(
    const float* __restrict__ A, const float* __restrict__ Wk,
    const float* __restrict__ Wv, float* __restrict__ P)
{
    __shared__ float sA[Lc][64];
    const int nb = blockIdx.x, ks = blockIdx.y, z = blockIdx.z;
    const float* W = z ? Wv : Wk;
    const int t = threadIdx.x;

    for (int idx = t; idx < Lc * 64; idx += 128) {
        int l = idx >> 6, kk = idx & 63;
        sA[l][kk] = A[l * Dc + ks * 64 + kk];
    }
    __syncthreads();

    const int n = nb * 128 + t;
    float acc[Lc];
    #pragma unroll
    for (int l = 0; l < Lc; l++) acc[l] = 0.f;

    #pragma unroll 8
    for (int kk = 0; kk < 64; kk++) {
        float wv = W[(size_t)(ks * 64 + kk) * Dc + n];
        #pragma unroll
        for (int l = 0; l < Lc; l++)
            acc[l] += sA[l][kk] * wv;
    }

    float* p = &P[((size_t)(z * 32 + ks) * Lc) * Dc + n];
    #pragma unroll
    for (int l = 0; l < Lc; l++)
        p[(size_t)l * Dc] = acc[l];
}

// Fused reduce: sums 32 k-split partials for both weights.
__global__ __launch_bounds__(256) void adapter_reduce2_kernel(
    const float* __restrict__ P, float* __restrict__ AK,
    float* __restrict__ AV)
{
    int idx = blockIdx.x * 256 + threadIdx.x;   // 0 .. 2*Lc*Dc-1
    int z = idx / (Lc * Dc);
    int r = idx - z * Lc * Dc;                  // l*Dc + n
    float s = 0.f;
    #pragma unroll
    for (int ks = 0; ks < 32; ks++)
        s += P[((size_t)(z * 32 + ks) * Lc) * Dc + r];
    if (z == 0) AK[r] = s; else AV[r] = s;
}

// ---------------------------------------------------------------------------
// Adapter attention: one warp per (b,s,h). Writes (not RMW).
// ---------------------------------------------------------------------------
__global__ __launch_bounds__(256) void adapter_attn_kernel(
    const float* __restrict__ gate)
{
    int gw = (blockIdx.x * blockDim.x + threadIdx.x) >> 5;
    int lane = threadIdx.x & 31;
    if (gw >= Bc * Sc * Hc) return;
    int h = gw % Hc;
    int s = (gw / Hc) % Sc;
    int b = gw / (Hc * Sc);

    size_t qoff = ((size_t)(b * Sc + s)) * Dc + h * HDc + lane * 4;
    __nv_bfloat162 qh01 = ((const __nv_bfloat162*)g_qh)[qoff >> 1];
    __nv_bfloat162 qh23 = ((const __nv_bfloat162*)g_qh)[(qoff >> 1) + 1];
    __nv_bfloat162 ql01 = ((const __nv_bfloat162*)g_ql)[qoff >> 1];
    __nv_bfloat162 ql23 = ((const __nv_bfloat162*)g_ql)[(qoff >> 1) + 1];
    float4 q4;
    q4.x = __bfloat162float(qh01.x) + __bfloat162float(ql01.x);
    q4.y = __bfloat162float(qh01.y) + __bfloat162float(ql01.y);
    q4.z = __bfloat162float(qh23.x) + __bfloat162float(ql23.x);
    q4.w = __bfloat162float(qh23.y) + __bfloat162float(ql23.y);

    float scv[Lc];
    #pragma unroll
    for (int l = 0; l < Lc; l++) {
        float4 a4 = *(const float4*)(g_ak + (size_t)l * Dc + h * HDc + lane * 4);
        float p = q4.x * a4.x + q4.y * a4.y + q4.z * a4.z + q4.w * a4.w;
        #pragma unroll
        for (int o = 16; o > 0; o >>= 1)
            p += __shfl_xor_sync(0xffffffffu, p, o);
        scv[l] = p * SCALE;
    }
    float m = scv[0];
    #pragma unroll
    for (int l = 1; l < Lc; l++) m = fmaxf(m, scv[l]);
    float sum = 0.f;
    float e[Lc];
    #pragma unroll
    for (int l = 0; l < Lc; l++) { e[l] = expf(scv[l] - m); sum += e[l]; }
    float g = gate[h] / sum;

    float4 acc = make_float4(0.f, 0.f, 0.f, 0.f);
    #pragma unroll
    for (int l = 0; l < Lc; l++) {
        float4 a4 = *(const float4*)(g_av + (size_t)l * Dc + h * HDc + lane * 4);
        acc.x += e[l] * a4.x;
        acc.y += e[l] * a4.y;
        acc.z += e[l] * a4.z;
        acc.w += e[l] * a4.w;
    }
    float4 o4;
    o4.x = g * acc.x; o4.y = g * acc.y;
    o4.z = g * acc.z; o4.w = g * acc.w;
    *(float4*)(g_attn + qoff) = o4;
}

// ---------------------------------------------------------------------------
extern "C" void kernel_launch(void* const* d_in, const int* in_sizes, int n_in,
                              void* d_out, int out_size)
{
    const float* x       = (const float*)d_in[0];
    const float* wq      = (const float*)d_in[1];
    const float* wk      = (const float*)d_in[2];
    const float* wv      = (const float*)d_in[3];
    const float* wo      = (const float*)d_in[4];
    const float* adapter = (const float*)d_in[5];
    const float* gate    = (const float*)d_in[6];
    const float* fcos    = (const float*)d_in[7];
    const float* fsin    = (const float*)d_in[8];
    float* out = (float*)d_out;

    float *ak, *av, *part;
    __nv_bfloat16 *xh, *xl, *wth, *wtl, *qh, *ql, *kh, *kl, *vh, *vl;
    cudaGetSymbolAddress((void**)&ak,   g_ak);
    cudaGetSymbolAddress((void**)&av,   g_av);
    cudaGetSymbolAddress((void**)&part, g_partial);
    cudaGetSymbolAddress((void**)&xh,   g_xh);
    cudaGetSymbolAddress((void**)&xl,   g_xl);
    cudaGetSymbolAddress((void**)&wth,  g_wth);
    cudaGetSymbolAddress((void**)&wtl,  g_wtl);
    cudaGetSymbolAddress((void**)&qh,   g_qh);
    cudaGetSymbolAddress((void**)&ql,   g_ql);
    cudaGetSymbolAddress((void**)&kh,   g_kh);
    cudaGetSymbolAddress((void**)&kl,   g_kl);
    cudaGetSymbolAddress((void**)&vh,   g_vh);
    cudaGetSymbolAddress((void**)&vl,   g_vl);

    const int M = Bc * Sc;   // 4096

    cudaFuncSetAttribute(mma_gemm_kernel,
                         cudaFuncAttributeMaxDynamicSharedMemorySize,
                         GEMM_SMEM);
    cudaFuncSetAttribute(flash_mma_kernel,
                         cudaFuncAttributeMaxDynamicSharedMemorySize,
                         FLASH_SMEM);

    // persistent side stream + events for graph-capture fork/join
    static cudaStream_t s_side = nullptr;
    static cudaEvent_t e_fork = nullptr, e_wt = nullptr, e_join = nullptr;
    if (s_side == nullptr) {
        cudaStreamCreateWithFlags(&s_side, cudaStreamNonBlocking);
        cudaEventCreateWithFlags(&e_fork, cudaEventDisableTiming);
        cudaEventCreateWithFlags(&e_wt,   cudaEventDisableTiming);
        cudaEventCreateWithFlags(&e_join, cudaEventDisableTiming);
    }

    // fork side stream from the capture (default) stream
    cudaEventRecord(e_fork, 0);
    cudaStreamWaitEvent(s_side, e_fork, 0);

    // main: split x -> bf16 hi/lo
    split_kernel<<<(M * Dc / 4) / 256, 256>>>(x, xh, xl);

    // side: weight transposes, then adapter projections + reduce
    wtrans4_kernel<<<dim3(Dc / 64, Dc / 32, 4), 256, 0, s_side>>>(
        wq, wk, wv, wo, wth, wtl);
    cudaEventRecord(e_wt, s_side);
    adapter_proj2_kernel<<<dim3(Dc / 128, 32, 2), 128, 0, s_side>>>(
        adapter, wk, wv, part);
    adapter_reduce2_kernel<<<(2 * Lc * Dc) / 256, 256, 0, s_side>>>(
        part, ak, av);
    cudaEventRecord(e_join, s_side);

    // main: QKV GEMM needs split (main) + wtrans (side)
    cudaStreamWaitEvent(0, e_wt, 0);
    mma_gemm_kernel<<<dim3(3 * Dc / 128, M / 128), 256, GEMM_SMEM>>>(
        xh, xl, wth, wtl, fcos, fsin, qh, ql, kh, kl, vh, vl, nullptr, 0, Dc);

    // main: adapter attention needs qh/ql (main) + ak/av (side)
    cudaStreamWaitEvent(0, e_join, 0);
    adapter_attn_kernel<<<(Bc * Sc * Hc * 32) / 256, 256>>>(gate);

    // flash adds adapter term in epilogue and emits xh/xl split
    flash_mma_kernel<<<dim3(Sc / 128, Hc, Bc), 256, FLASH_SMEM>>>();

    // output projection (weights already transposed into segment 3)
    mma_gemm_kernel<<<dim3(Dc / 128, M / 128), 256, GEMM_SMEM>>>(
        xh, xl, wth + (size_t)3 * Dc * Dc, wtl + (size_t)3 * Dc * Dc,
        fcos, fsin, nullptr, nullptr, nullptr, nullptr, nullptr, nullptr,
        out, 1, Dc);
}

// round 16
// speedup vs baseline: 1.0033x; 1.0033x over previous
#include <cuda_runtime.h>
#include <cuda_bf16.h>
#include <math.h>
#include <stdint.h>

#define Bc 2
#define Sc 2048
#define Dc 2048
#define Hc 16
#define HDc 128
#define Lc 10

// Scratch (static device globals — allocation-free per harness rules)
__device__ float g_attn[Bc*Sc*Dc];
__device__ float g_ak[Lc*Dc];
__device__ float g_av[Lc*Dc];
__device__ float g_partial[2*32*Lc*Dc];
// bf16 split scratch
__device__ __nv_bfloat16 g_xh[Bc*Sc*Dc];   // x split; later attn split
__device__ __nv_bfloat16 g_xl[Bc*Sc*Dc];
__device__ __nv_bfloat16 g_wth[4*Dc*Dc];   // stacked W^T hi [wq|wk|wv|wo]
__device__ __nv_bfloat16 g_wtl[4*Dc*Dc];   // stacked W^T lo
__device__ __nv_bfloat16 g_qh[Bc*Sc*Dc];
__device__ __nv_bfloat16 g_ql[Bc*Sc*Dc];
__device__ __nv_bfloat16 g_kh[Bc*Sc*Dc];
__device__ __nv_bfloat16 g_kl[Bc*Sc*Dc];
__device__ __nv_bfloat16 g_vh[Bc*Sc*Dc];   // [B,S,H,HD] (same layout as K)
__device__ __nv_bfloat16 g_vl[Bc*Sc*Dc];

#define SCALE 0.08838834764831845f  // 1/sqrt(128)

// ---------------------------------------------------------------------------
// mma.sync + ldmatrix + cp.async helpers
// ---------------------------------------------------------------------------
#define MMA16816(c, a0, a1, a2, a3, b0, b1) \
    asm volatile( \
        "mma.sync.aligned.m16n8k16.row.col.f32.bf16.bf16.f32 " \
        "{%0,%1,%2,%3}, {%4,%5,%6,%7}, {%8,%9}, {%0,%1,%2,%3};" \
        : "+f"((c)[0]), "+f"((c)[1]), "+f"((c)[2]), "+f"((c)[3]) \
        : "r"(a0), "r"(a1), "r"(a2), "r"(a3), "r"(b0), "r"(b1))

#define LDSM4(r0, r1, r2, r3, addr) \
    asm volatile("ldmatrix.sync.aligned.m8n8.x4.shared.b16 {%0,%1,%2,%3}, [%4];" \
                 : "=r"(r0), "=r"(r1), "=r"(r2), "=r"(r3) : "r"(addr))

#define LDSM4T(r0, r1, r2, r3, addr) \
    asm volatile("ldmatrix.sync.aligned.m8n8.x4.trans.shared.b16 {%0,%1,%2,%3}, [%4];" \
                 : "=r"(r0), "=r"(r1), "=r"(r2), "=r"(r3) : "r"(addr))

__device__ __forceinline__ uint32_t smem_u32(const void* p) {
    uint32_t a;
    asm("{ .reg .u64 t; cvta.to.shared.u64 t, %1; cvt.u32.u64 %0, t; }"
        : "=r"(a) : "l"(p));
    return a;
}
#define CPA16(saddr, gptr) \
    asm volatile("cp.async.cg.shared.global [%0], [%1], 16;" \
                 :: "r"(saddr), "l"(gptr))
#define CPA_COMMIT() asm volatile("cp.async.commit_group;")
#define CPA_WAIT(n)  asm volatile("cp.async.wait_group %0;" :: "n"(n))

__device__ __forceinline__ __nv_bfloat162 bsplit_hi(float a, float b) {
    __nv_bfloat162 r;
    r.x = __float2bfloat16(a);
    r.y = __float2bfloat16(b);
    return r;
}
__device__ __forceinline__ __nv_bfloat162 bsplit_lo(float a, float b,
                                                    __nv_bfloat162 h) {
    __nv_bfloat162 r;
    r.x = __float2bfloat16(a - __bfloat162float(h.x));
    r.y = __float2bfloat16(b - __bfloat162float(h.y));
    return r;
}

// ---------------------------------------------------------------------------
// Elementwise fp32 -> bf16 hi/lo split (x only)
// ---------------------------------------------------------------------------
__global__ __launch_bounds__(256) void split_kernel(
    const float* __restrict__ x, __nv_bfloat16* __restrict__ h,
    __nv_bfloat16* __restrict__ l)
{
    int i = blockIdx.x * 256 + threadIdx.x;
    float4 v = ((const float4*)x)[i];
    __nv_bfloat162 h01 = bsplit_hi(v.x, v.y);
    __nv_bfloat162 h23 = bsplit_hi(v.z, v.w);
    ((__nv_bfloat162*)h)[i * 2 + 0] = h01;
    ((__nv_bfloat162*)h)[i * 2 + 1] = h23;
    ((__nv_bfloat162*)l)[i * 2 + 0] = bsplit_lo(v.x, v.y, h01);
    ((__nv_bfloat162*)l)[i * 2 + 1] = bsplit_lo(v.z, v.w, h23);
}

// ---------------------------------------------------------------------------
// Transpose + split, 4 weights in one launch (blockIdx.z selects).
// ---------------------------------------------------------------------------
__global__ __launch_bounds__(256) void wtrans4_kernel(
    const float* __restrict__ W0, const float* __restrict__ W1,
    const float* __restrict__ W2, const float* __restrict__ W3,
    __nv_bfloat16* __restrict__ Th, __nv_bfloat16* __restrict__ Tl)
{
    __shared__ float tile[64][33];
    const int z = blockIdx.z;
    const float* W = (z == 0) ? W0 : (z == 1) ? W1 : (z == 2) ? W2 : W3;
    __nv_bfloat16* Tho = Th + (size_t)z * Dc * Dc;
    __nv_bfloat16* Tlo = Tl + (size_t)z * Dc * Dc;
    const int k0 = blockIdx.x * 64, n0 = blockIdx.y * 32;
    const int t = threadIdx.x;
    const int r = t >> 5, c = t & 31;
    #pragma unroll
    for (int i = 0; i < 8; i++)
        tile[r + i * 8][c] = W[(size_t)(k0 + r + i * 8) * Dc + n0 + c];
    __syncthreads();
    #pragma unroll
    for (int i = 0; i < 4; i++) {
        int n = r * 4 + i;
        float v0 = tile[2 * c][n];
        float v1 = tile[2 * c + 1][n];
        __nv_bfloat162 hh = bsplit_hi(v0, v1);
        size_t o = ((size_t)(n0 + n) * Dc + k0) >> 1;
        ((__nv_bfloat162*)Tho)[o + c] = hh;
        ((__nv_bfloat162*)Tlo)[o + c] = bsplit_lo(v0, v1, hh);
    }
}

// ---------------------------------------------------------------------------
// bf16x3 tensor-core GEMM, BK=64, 2-stage cp.async + ldmatrix.  (R14 config)
// ---------------------------------------------------------------------------
#define SROW2 72
#define STG2 36864                         // elems per stage (4 * 128 * 72)
#define GEMM_SMEM (2 * STG2 * 2)           // 147456 bytes

__global__ __launch_bounds__(256, 1) void mma_gemm_kernel(
    const __nv_bfloat16* __restrict__ Ah, const __nv_bfloat16* __restrict__ Al,
    const __nv_bfloat16* __restrict__ BhT, const __nv_bfloat16* __restrict__ BlT,
    const float* __restrict__ fc, const float* __restrict__ fs,
    __nv_bfloat16* __restrict__ oQh, __nv_bfloat16* __restrict__ oQl,
    __nv_bfloat16* __restrict__ oKh, __nv_bfloat16* __restrict__ oKl,
    __nv_bfloat16* __restrict__ oVh, __nv_bfloat16* __restrict__ oVl,
    float* __restrict__ oC, int mode, int K)
{
    extern __shared__ __align__(16) __nv_bfloat16 dsm[];
    const uint32_t sb = smem_u32(dsm);

    const int t = threadIdx.x, lane = t & 31, wid = t >> 5;
    const int wm = wid & 1, wn = wid >> 1;
    const int bm = blockIdx.y * 128, bn = blockIdx.x * 128;
    const int gid = lane >> 2, tig = lane & 3;

    const int aoffE = (wm * 64 + (lane & 15)) * SROW2 + ((lane >> 4) & 1) * 8;
    const int boffE = (wn * 32 + ((lane >> 4) & 1) * 8 + (lane & 7)) * SROW2
                    + ((lane >> 3) & 1) * 8;

    float acc[4][4][4];
    #pragma unroll
    for (int a = 0; a < 4; a++)
        #pragma unroll
        for (int b = 0; b < 4; b++)
            #pragma unroll
            for (int cc = 0; cc < 4; cc++) acc[a][b][cc] = 0.f;

    const int nst = K >> 6;

    #define LOAD_STAGE2(stg, k0) do {                                       \
        uint32_t base = sb + (stg) * STG2 * 2;                              \
        _Pragma("unroll")                                                   \
        for (int jj = 0; jj < 4; jj++) {                                    \
            int u = t + jj * 256;                                           \
            int row = u >> 3, ch = (u & 7) * 8;                             \
            size_t ga = (size_t)(bm + row) * K + (k0) + ch;                 \
            size_t gb = (size_t)(bn + row) * K + (k0) + ch;                 \
            CPA16(base + (row * SROW2 + ch) * 2, &Ah[ga]);                  \
            CPA16(base + (9216 + row * SROW2 + ch) * 2, &Al[ga]);           \
            CPA16(base + (18432 + row * SROW2 + ch) * 2, &BhT[gb]);         \
            CPA16(base + (27648 + row * SROW2 + ch) * 2, &BlT[gb]);         \
        }                                                                   \
        CPA_COMMIT();                                                       \
    } while (0)

    LOAD_STAGE2(0, 0);
    LOAD_STAGE2(1, 64);

    for (int it = 0; it < nst; it++) {
        if (it == nst - 1) { CPA_WAIT(0); } else { CPA_WAIT(1); }
        __syncthreads();

        const uint32_t base = sb + (it & 1) * STG2 * 2;

        #pragma unroll
        for (int ks = 0; ks < 4; ks++) {
            uint32_t ah[4][4], al[4][4];
            #pragma unroll
            for (int mt = 0; mt < 4; mt++) {
                uint32_t aaddr = base + (aoffE + mt * 16 * SROW2 + ks * 16) * 2;
                LDSM4(ah[mt][0], ah[mt][1], ah[mt][2], ah[mt][3], aaddr);
                LDSM4(al[mt][0], al[mt][1], al[mt][2], al[mt][3],
                      aaddr + 9216 * 2);
            }
            #pragma unroll
            for (int ntp = 0; ntp < 2; ntp++) {
                uint32_t baddr = base +
                    (18432 + boffE + ntp * 16 * SROW2 + ks * 16) * 2;
                uint32_t bh0, bh1, bh2, bh3, bl0, bl1, bl2, bl3;
                LDSM4(bh0, bh1, bh2, bh3, baddr);
                LDSM4(bl0, bl1, bl2, bl3, baddr + 9216 * 2);
                #pragma unroll
                for (int mt = 0; mt < 4; mt++) {
                    MMA16816(acc[mt][2 * ntp],     ah[mt][0], ah[mt][1], ah[mt][2], ah[mt][3], bh0, bh1);
                    MMA16816(acc[mt][2 * ntp + 1], ah[mt][0], ah[mt][1], ah[mt][2], ah[mt][3], bh2, bh3);
                    MMA16816(acc[mt][2 * ntp],     ah[mt][0], ah[mt][1], ah[mt][2], ah[mt][3], bl0, bl1);
                    MMA16816(acc[mt][2 * ntp + 1], ah[mt][0], ah[mt][1], ah[mt][2], ah[mt][3], bl2, bl3);
                    MMA16816(acc[mt][2 * ntp],     al[mt][0], al[mt][1], al[mt][2], al[mt][3], bh0, bh1);
                    MMA16816(acc[mt][2 * ntp + 1], al[mt][0], al[mt][1], al[mt][2], al[mt][3], bh2, bh3);
                }
            }
        }
        __syncthreads();
        if (it + 2 < nst) {
            LOAD_STAGE2((it + 2) & 1, (it + 2) * 64);
        }
    }

    // ---- epilogue ----
    #pragma unroll
    for (int mt = 0; mt < 4; mt++) {
        int row = bm + wm * 64 + mt * 16 + gid;
        #pragma unroll
        for (int nt = 0; nt < 4; nt++) {
            int colg = bn + wn * 32 + nt * 8 + tig * 2;
            float a0 = acc[mt][nt][0], a1 = acc[mt][nt][1];
            float a2 = acc[mt][nt][2], a3 = acc[mt][nt][3];
            if (mode == 1) {
                *(float2*)&oC[(size_t)row * Dc + colg] = make_float2(a0, a1);
                *(float2*)&oC[(size_t)(row + 8) * Dc + colg] = make_float2(a2, a3);
            } else {
                int seg = colg >> 11;
                int d = colg & 2047;
                float r00 = a0, r01 = a1, r10 = a2, r11 = a3;
                if (seg < 2) {   // RoPE for Q and K
                    int s0 = row & 2047, s1 = (row + 8) & 2047;
                    int j = (d & 127) >> 1;
                    float c0 = fc[s0 * 64 + j], n0 = fs[s0 * 64 + j];
                    float c1 = fc[s1 * 64 + j], n1 = fs[s1 * 64 + j];
                    r00 = a0 * c0 - a1 * n0; r01 = a0 * n0 + a1 * c0;
                    r10 = a2 * c1 - a3 * n1; r11 = a2 * n1 + a3 * c1;
                }
                __nv_bfloat16* dH = (seg == 0) ? oQh : (seg == 1) ? oKh : oVh;
                __nv_bfloat16* dL = (seg == 0) ? oQl : (seg == 1) ? oKl : oVl;
                size_t o0 = ((size_t)row * Dc + d) >> 1;
                size_t o1 = ((size_t)(row + 8) * Dc + d) >> 1;
                __nv_bfloat162 h0 = bsplit_hi(r00, r01);
                __nv_bfloat162 h1 = bsplit_hi(r10, r11);
                ((__nv_bfloat162*)dH)[o0] = h0;
                ((__nv_bfloat162*)dH)[o1] = h1;
                ((__nv_bfloat162*)dL)[o0] = bsplit_lo(r00, r01, h0);
                ((__nv_bfloat162*)dL)[o1] = bsplit_lo(r10, r11, h1);
            }
        }
    }
}

// ---------------------------------------------------------------------------
// Flash attention (bf16x3), ldmatrix (+trans for V), 2-stage K/V pipeline.
// ---------------------------------------------------------------------------
#define FQS 136
#define FQ_ELEMS (2 * 128 * FQS)              // Qh+Ql
#define FKV_ELEMS (4 * 64 * FQS)              // Kh,Kl,Vh,Vl each 64x136
#define FLASH_SMEM ((FQ_ELEMS + 2 * FKV_ELEMS) * 2)   // 208896 bytes

__global__ __launch_bounds__(256, 1) void flash_mma_kernel()
{
    extern __shared__ __align__(16) __nv_bfloat16 fsm[];
    __nv_bfloat16* sQh = fsm;
    __nv_bfloat16* sQl = sQh + 128 * FQS;
    const uint32_t uQh = smem_u32(sQh), uQl = smem_u32(sQl);
    const uint32_t uS0 = uQh + FQ_ELEMS * 2;

    const int t = threadIdx.x, lane = t & 31, w = t >> 5;
    const int gid = lane >> 2, tig = lane & 3;
    const int qt = gridDim.x - 1 - blockIdx.x;   // longest first
    const int h = blockIdx.y, b = blockIdx.z;
    const int qbase = qt * 128;

    const int qaoffE = (w * 16 + (lane & 15)) * FQS + ((lane >> 4) & 1) * 8;
    const int kboffE = (((lane >> 4) & 1) * 8 + (lane & 7)) * FQS
                     + ((lane >> 3) & 1) * 8;
    const int vboffE = (lane & 15) * FQS + ((lane >> 4) & 1) * 8;

    #pragma unroll
    for (int i = 0; i < 8; i++) {
        int u = t + i * 256;
        int row = u >> 4, c8 = (u & 15) * 8;
        size_t g = ((size_t)(b * Sc + qbase + row)) * Dc + h * HDc + c8;
        *(uint4*)&sQh[row * FQS + c8] = *(const uint4*)&g_qh[g];
        *(uint4*)&sQl[row * FQS + c8] = *(const uint4*)&g_ql[g];
    }

    const int row0 = qbase + w * 16 + gid;
    const int row1 = row0 + 8;

    float m0 = -1e30f, m1 = -1e30f, l0 = 0.f, l1 = 0.f;
    float oacc[16][4];
    #pragma unroll
    for (int i = 0; i < 16; i++)
        #pragma unroll
        for (int j = 0; j < 4; j++) oacc[i][j] = 0.f;

    const int ntk = 2 * qt + 2;

    #define LOAD_KV(kt_) do {                                               \
        const uint32_t sb2 = uS0 + ((kt_) & 1) * FKV_ELEMS * 2;             \
        const int kb_ = (kt_) * 64;                                         \
        _Pragma("unroll")                                                   \
        for (int i = 0; i < 4; i++) {                                       \
            int u = t + i * 256;                                            \
            int krow = u >> 4, c8 = (u & 15) * 8;                           \
            size_t gk = ((size_t)(b * Sc + kb_ + krow)) * Dc + h * HDc + c8;\
            CPA16(sb2 + (krow * FQS + c8) * 2, &g_kh[gk]);                  \
            CPA16(sb2 + (8704 + krow * FQS + c8) * 2, &g_kl[gk]);           \
            CPA16(sb2 + (17408 + krow * FQS + c8) * 2, &g_vh[gk]);          \
            CPA16(sb2 + (26112 + krow * FQS + c8) * 2, &g_vl[gk]);          \
        }                                                                   \
        CPA_COMMIT();                                                       \
    } while (0)

    LOAD_KV(0);

    for (int kt = 0; kt < ntk; kt++) {
        const int kbase = kt * 64;
        if (kt + 1 < ntk) {
            LOAD_KV(kt + 1);
            CPA_WAIT(1);
        } else {
            CPA_WAIT(0);
        }
        __syncthreads();

        const uint32_t sb2 = uS0 + (kt & 1) * FKV_ELEMS * 2;
        const uint32_t uKh2 = sb2, uKl2 = sb2 + 8704 * 2;
        const uint32_t uVh2 = sb2 + 17408 * 2, uVl2 = sb2 + 26112 * 2;

        float sacc[8][4];
        #pragma unroll
        for (int nt = 0; nt < 8; nt++)
            #pragma unroll
            for (int j = 0; j < 4; j++) sacc[nt][j] = 0.f;

        #pragma unroll
        for (int kc = 0; kc < 8; kc++) {
            uint32_t ah0, ah1, ah2, ah3, al0, al1, al2, al3;
            LDSM4(ah0, ah1, ah2, ah3, uQh + (qaoffE + kc * 16) * 2);
            LDSM4(al0, al1, al2, al3, uQl + (qaoffE + kc * 16) * 2);
            #pragma unroll
            for (int ntp = 0; ntp < 4; ntp++) {
                uint32_t kaddr = (kboffE + ntp * 16 * FQS + kc * 16) * 2;
                uint32_t bh0, bh1, bh2, bh3, bl0, bl1, bl2, bl3;
                LDSM4(bh0, bh1, bh2, bh3, uKh2 + kaddr);
                LDSM4(bl0, bl1, bl2, bl3, uKl2 + kaddr);
                MMA16816(sacc[2 * ntp],     ah0, ah1, ah2, ah3, bh0, bh1);
                MMA16816(sacc[2 * ntp + 1], ah0, ah1, ah2, ah3, bh2, bh3);
                MMA16816(sacc[2 * ntp],     ah0, ah1, ah2, ah3, bl0, bl1);
                MMA16816(sacc[2 * ntp + 1], ah0, ah1, ah2, ah3, bl2, bl3);
                MMA16816(sacc[2 * ntp],     al0, al1, al2, al3, bh0, bh1);
                MMA16816(sacc[2 * ntp + 1], al0, al1, al2, al3, bh2, bh3);
            }
        }

        const bool need_mask = (kt >= 2 * qt);
        #pragma unroll
        for (int nt = 0; nt < 8; nt++) {
            int c0 = kbase + nt * 8 + 2 * tig;
            float v0 = sacc[nt][0] * SCALE;
            float v1 = sacc[nt][1] * SCALE;
            float v2 = sacc[nt][2] * SCALE;
            float v3 = sacc[nt][3] * SCALE;
            if (need_mask) {
                if (c0 > row0)     v0 -= 1e9f;
                if (c0 + 1 > row0) v1 -= 1e9f;
                if (c0 > row1)     v2 -= 1e9f;
                if (c0 + 1 > row1) v3 -= 1e9f;
            }
            sacc[nt][0] = v0; sacc[nt][1] = v1;
            sacc[nt][2] = v2; sacc[nt][3] = v3;
        }

        float mx0 = -1e30f, mx1 = -1e30f;
        #pragma unroll
        for (int nt = 0; nt < 8; nt++) {
            mx0 = fmaxf(mx0, fmaxf(sacc[nt][0], sacc[nt][1]));
            mx1 = fmaxf(mx1, fmaxf(sacc[nt][2], sacc[nt][3]));
        }
        mx0 = fmaxf(mx0, __shfl_xor_sync(0xffffffffu, mx0, 1));
        mx0 = fmaxf(mx0, __shfl_xor_sync(0xffffffffu, mx0, 2));
        mx1 = fmaxf(mx1, __shfl_xor_sync(0xffffffffu, mx1, 1));
        mx1 = fmaxf(mx1, __shfl_xor_sync(0xffffffffu, mx1, 2));
        float nm0 = fmaxf(m0, mx0), nm1 = fmaxf(m1, mx1);
        float corr0 = __expf(m0 - nm0), corr1 = __expf(m1 - nm1);
        m0 = nm0; m1 = nm1;

        float rs0 = 0.f, rs1 = 0.f;
        uint32_t ph01[8], ph23[8], pl01[8], pl23[8];
        #pragma unroll
        for (int nt = 0; nt < 8; nt++) {
            float e0 = __expf(sacc[nt][0] - nm0);
            float e1 = __expf(sacc[nt][1] - nm0);
            float e2 = __expf(sacc[nt][2] - nm1);
            float e3 = __expf(sacc[nt][3] - nm1);
            rs0 += e0 + e1; rs1 += e2 + e3;
            __nv_bfloat162 h01 = __floats2bfloat162_rn(e0, e1);
            __nv_bfloat162 h23 = __floats2bfloat162_rn(e2, e3);
            __nv_bfloat162 lo01 = __floats2bfloat162_rn(
                e0 - __bfloat162float(h01.x), e1 - __bfloat162float(h01.y));
            __nv_bfloat162 lo23 = __floats2bfloat162_rn(
                e2 - __bfloat162float(h23.x), e3 - __bfloat162float(h23.y));
            ph01[nt] = *(uint32_t*)&h01;
            ph23[nt] = *(uint32_t*)&h23;
            pl01[nt] = *(uint32_t*)&lo01;
            pl23[nt] = *(uint32_t*)&lo23;
        }
        rs0 += __shfl_xor_sync(0xffffffffu, rs0, 1);
        rs0 += __shfl_xor_sync(0xffffffffu, rs0, 2);
        rs1 += __shfl_xor_sync(0xffffffffu, rs1, 1);
        rs1 += __shfl_xor_sync(0xffffffffu, rs1, 2);
        l0 = l0 * corr0 + rs0;
        l1 = l1 * corr1 + rs1;

        #pragma unroll
        for (int nto = 0; nto < 16; nto++) {
            oacc[nto][0] *= corr0; oacc[nto][1] *= corr0;
            oacc[nto][2] *= corr1; oacc[nto][3] *= corr1;
        }

        // ---- O += P V (V fragments via ldmatrix.trans from [s][d]) ----
        #pragma unroll
        for (int j = 0; j < 4; j++) {
            uint32_t a0h = ph01[2 * j],     a1h = ph23[2 * j];
            uint32_t a2h = ph01[2 * j + 1], a3h = ph23[2 * j + 1];
            uint32_t a0l = pl01[2 * j],     a1l = pl23[2 * j];
            uint32_t a2l = pl01[2 * j + 1], a3l = pl23[2 * j + 1];
            #pragma unroll
            for (int ntp = 0; ntp < 4; ntp++) {
                uint32_t vaddr = (vboffE + j * 16 * FQS + ntp * 32) * 2;
                uint32_t vh0, vh1, vh2, vh3, vl0, vl1, vl2, vl3;
                LDSM4T(vh0, vh1, vh2, vh3, uVh2 + vaddr);
                LDSM4T(vl0, vl1, vl2, vl3, uVl2 + vaddr);
                MMA16816(oacc[4 * ntp],     a0h, a1h, a2h, a3h, vh0, vh1);
                MMA16816(oacc[4 * ntp + 1], a0h, a1h, a2h, a3h, vh2, vh3);
                MMA16816(oacc[4 * ntp],     a0h, a1h, a2h, a3h, vl0, vl1);
                MMA16816(oacc[4 * ntp + 1], a0h, a1h, a2h, a3h, vl2, vl3);
                MMA16816(oacc[4 * ntp],     a0l, a1l, a2l, a3l, vh0, vh1);
                MMA16816(oacc[4 * ntp + 1], a0l, a1l, a2l, a3l, vh2, vh3);

                uint32_t vaddr2 = (vboffE + j * 16 * FQS + ntp * 32 + 16) * 2;
                uint32_t wh0, wh1, wh2, wh3, wl0, wl1, wl2, wl3;
                LDSM4T(wh0, wh1, wh2, wh3, uVh2 + vaddr2);
                LDSM4T(wl0, wl1, wl2, wl3, uVl2 + vaddr2);
                MMA16816(oacc[4 * ntp + 2], a0h, a1h, a2h, a3h, wh0, wh1);
                MMA16816(oacc[4 * ntp + 3], a0h, a1h, a2h, a3h, wh2, wh3);
                MMA16816(oacc[4 * ntp + 2], a0h, a1h, a2h, a3h, wl0, wl1);
                MMA16816(oacc[4 * ntp + 3], a0h, a1h, a2h, a3h, wl2, wl3);
                MMA16816(oacc[4 * ntp + 2], a0l, a1l, a2l, a3l, wh0, wh1);
                MMA16816(oacc[4 * ntp + 3], a0l, a1l, a2l, a3l, wh2, wh3);
            }
        }
        __syncthreads();
    }

    // ---- epilogue: add adapter contribution, emit bf16 hi/lo split ----
    float i0 = 1.f / l0, i1 = 1.f / l1;
    #pragma unroll
    for (int nto = 0; nto < 16; nto++) {
        int col = h * HDc + nto * 8 + 2 * tig;
        size_t o0 = ((size_t)(b * Sc + row0)) * Dc + col;
        size_t o1 = ((size_t)(b * Sc + row1)) * Dc + col;
        float2 ad0 = *(const float2*)&g_attn[o0];
        float2 ad1 = *(const float2*)&g_attn[o1];
        float f00 = oacc[nto][0] * i0 + ad0.x;
        float f01 = oacc[nto][1] * i0 + ad0.y;
        float f10 = oacc[nto][2] * i1 + ad1.x;
        float f11 = oacc[nto][3] * i1 + ad1.y;
        __nv_bfloat162 h0 = bsplit_hi(f00, f01);
        __nv_bfloat162 h1 = bsplit_hi(f10, f11);
        ((__nv_bfloat162*)g_xh)[o0 >> 1] = h0;
        ((__nv_bfloat162*)g_xh)[o1 >> 1] = h1;
        ((__nv_bfloat162*)g_xl)[o0 >> 1] = bsplit_lo(f00, f01, h0);
        ((__nv_bfloat162*)g_xl)[o1 >> 1] = bsplit_lo(f10, f11, h1);
    }
}

// ---------------------------------------------------------------------------
// Adapter projection (both weights): grid (Dc/128, 32 k-splits, 2), 128 thr.
// ---------------------------------------------------------------------------
__global__ __launch_bounds__(128) void adapter_proj2_kernel(
    const float* __restrict__ A, const float* __restrict__ Wk,
    const float* __restrict__ Wv, float* __restrict__ P)
{
    __shared__ float sA[Lc][64];
    const int nb = blockIdx.x, ks = blockIdx.y, z = blockIdx.z;
    const float* W = z ? Wv : Wk;
    const int t = threadIdx.x;

    for (int idx = t; idx < Lc * 64; idx += 128) {
        int l = idx >> 6, kk = idx & 63;
        sA[l][kk] = A[l * Dc + ks * 64 + kk];
    }
    __syncthreads();

    const int n = nb * 128 + t;
    float acc[Lc];
    #pragma unroll
    for (int l = 0; l < Lc; l++) acc[l] = 0.f;

    #pragma unroll 8
    for (int kk = 0; kk < 64; kk++) {
        float wv = W[(size_t)(ks * 64 + kk) * Dc + n];
        #pragma unroll
        for (int l = 0; l < Lc; l++)
            acc[l] += sA[l][kk] * wv;
    }

    float* p = &P[((size_t)(z * 32 + ks) * Lc) * Dc + n];
    #pragma unroll
    for (int l = 0; l < Lc; l++)
        p[(size_t)l * Dc] = acc[l];
}

// Fused reduce: sums 32 k-split partials for both weights.
__global__ __launch_bounds__(256) void adapter_reduce2_kernel(
    const float* __restrict__ P, float* __restrict__ AK,
    float* __restrict__ AV)
{
    int idx = blockIdx.x * 256 + threadIdx.x;   // 0 .. 2*Lc*Dc-1
    int z = idx / (Lc * Dc);
    int r = idx - z * Lc * Dc;                  // l*Dc + n
    float s = 0.f;
    #pragma unroll
    for (int ks = 0; ks < 32; ks++)
        s += P[((size_t)(z * 32 + ks) * Lc) * Dc + r];
    if (z == 0) AK[r] = s; else AV[r] = s;
}

// ---------------------------------------------------------------------------
// Adapter attention: one warp per (b,s,h). Writes (not RMW).
// ---------------------------------------------------------------------------
__global__ __launch_bounds__(256) void adapter_attn_kernel(
    const float* __restrict__ gate)
{
    int gw = (blockIdx.x * blockDim.x + threadIdx.x) >> 5;
    int lane = threadIdx.x & 31;
    if (gw >= Bc * Sc * Hc) return;
    int h = gw % Hc;
    int s = (gw / Hc) % Sc;
    int b = gw / (Hc * Sc);

    size_t qoff = ((size_t)(b * Sc + s)) * Dc + h * HDc + lane * 4;
    __nv_bfloat162 qh01 = ((const __nv_bfloat162*)g_qh)[qoff >> 1];
    __nv_bfloat162 qh23 = ((const __nv_bfloat162*)g_qh)[(qoff >> 1) + 1];
    __nv_bfloat162 ql01 = ((const __nv_bfloat162*)g_ql)[qoff >> 1];
    __nv_bfloat162 ql23 = ((const __nv_bfloat162*)g_ql)[(qoff >> 1) + 1];
    float4 q4;
    q4.x = __bfloat162float(qh01.x) + __bfloat162float(ql01.x);
    q4.y = __bfloat162float(qh01.y) + __bfloat162float(ql01.y);
    q4.z = __bfloat162float(qh23.x) + __bfloat162float(ql23.x);
    q4.w = __bfloat162float(qh23.y) + __bfloat162float(ql23.y);

    float scv[Lc];
    #pragma unroll
    for (int l = 0; l < Lc; l++) {
        float4 a4 = *(const float4*)(g_ak + (size_t)l * Dc + h * HDc + lane * 4);
        float p = q4.x * a4.x + q4.y * a4.y + q4.z * a4.z + q4.w * a4.w;
        #pragma unroll
        for (int o = 16; o > 0; o >>= 1)
            p += __shfl_xor_sync(0xffffffffu, p, o);
        scv[l] = p * SCALE;
    }
    float m = scv[0];
    #pragma unroll
    for (int l = 1; l < Lc; l++) m = fmaxf(m, scv[l]);
    float sum = 0.f;
    float e[Lc];
    #pragma unroll
    for (int l = 0; l < Lc; l++) { e[l] = expf(scv[l] - m); sum += e[l]; }
    float g = gate[h] / sum;

    float4 acc = make_float4(0.f, 0.f, 0.f, 0.f);
    #pragma unroll
    for (int l = 0; l < Lc; l++) {
        float4 a4 = *(const float4*)(g_av + (size_t)l * Dc + h * HDc + lane * 4);
        acc.x += e[l] * a4.x;
        acc.y += e[l] * a4.y;
        acc.z += e[l] * a4.z;
        acc.w += e[l] * a4.w;
    }
    float4 o4;
    o4.x = g * acc.x; o4.y = g * acc.y;
    o4.z = g * acc.z; o4.w = g * acc.w;
    *(float4*)(g_attn + qoff) = o4;
}

// ---------------------------------------------------------------------------
extern "C" void kernel_launch(void* const* d_in, const int* in_sizes, int n_in,
                              void* d_out, int out_size)
{
    const float* x       = (const float*)d_in[0];
    const float* wq      = (const float*)d_in[1];
    const float* wk      = (const float*)d_in[2];
    const float* wv      = (const float*)d_in[3];
    const float* wo      = (const float*)d_in[4];
    const float* adapter = (const float*)d_in[5];
    const float* gate    = (const float*)d_in[6];
    const float* fcos    = (const float*)d_in[7];
    const float* fsin    = (const float*)d_in[8];
    float* out = (float*)d_out;

    float *ak, *av, *part;
    __nv_bfloat16 *xh, *xl, *wth, *wtl, *qh, *ql, *kh, *kl, *vh, *vl;
    cudaGetSymbolAddress((void**)&ak,   g_ak);
    cudaGetSymbolAddress((void**)&av,   g_av);
    cudaGetSymbolAddress((void**)&part, g_partial);
    cudaGetSymbolAddress((void**)&xh,   g_xh);
    cudaGetSymbolAddress((void**)&xl,   g_xl);
    cudaGetSymbolAddress((void**)&wth,  g_wth);
    cudaGetSymbolAddress((void**)&wtl,  g_wtl);
    cudaGetSymbolAddress((void**)&qh,   g_qh);
    cudaGetSymbolAddress((void**)&ql,   g_ql);
    cudaGetSymbolAddress((void**)&kh,   g_kh);
    cudaGetSymbolAddress((void**)&kl,   g_kl);
    cudaGetSymbolAddress((void**)&vh,   g_vh);
    cudaGetSymbolAddress((void**)&vl,   g_vl);

    const int M = Bc * Sc;   // 4096

    cudaFuncSetAttribute(mma_gemm_kernel,
                         cudaFuncAttributeMaxDynamicSharedMemorySize,
                         GEMM_SMEM);
    cudaFuncSetAttribute(flash_mma_kernel,
                         cudaFuncAttributeMaxDynamicSharedMemorySize,
                         FLASH_SMEM);

    // persistent side stream + events for graph-capture fork/join
    static cudaStream_t s_side = nullptr;
    static cudaEvent_t e_fork = nullptr, e_wt = nullptr, e_join = nullptr;
    if (s_side == nullptr) {
        cudaStreamCreateWithFlags(&s_side, cudaStreamNonBlocking);
        cudaEventCreateWithFlags(&e_fork, cudaEventDisableTiming);
        cudaEventCreateWithFlags(&e_wt,   cudaEventDisableTiming);
        cudaEventCreateWithFlags(&e_join, cudaEventDisableTiming);
    }

    // fork side stream from the capture (default) stream
    cudaEventRecord(e_fork, 0);
    cudaStreamWaitEvent(s_side, e_fork, 0);

    // main: split x -> bf16 hi/lo
    split_kernel<<<(M * Dc / 4) / 256, 256>>>(x, xh, xl);

    // side: weight transposes, then adapter projections + reduce
    wtrans4_kernel<<<dim3(Dc / 64, Dc / 32, 4), 256, 0, s_side>>>(
        wq, wk, wv, wo, wth, wtl);
    cudaEventRecord(e_wt, s_side);
    adapter_proj2_kernel<<<dim3(Dc / 128, 32, 2), 128, 0, s_side>>>(
        adapter, wk, wv, part);
    adapter_reduce2_kernel<<<(2 * Lc * Dc) / 256, 256, 0, s_side>>>(
        part, ak, av);
    cudaEventRecord(e_join, s_side);

    // main: QKV GEMM needs split (main) + wtrans (side)
    cudaStreamWaitEvent(0, e_wt, 0);
    mma_gemm_kernel<<<dim3(3 * Dc / 128, M / 128), 256, GEMM_SMEM>>>(
        xh, xl, wth, wtl, fcos, fsin, qh, ql, kh, kl, vh, vl, nullptr, 0, Dc);

    // main: adapter attention needs qh/ql (main) + ak/av (side)
    cudaStreamWaitEvent(0, e_join, 0);
    adapter_attn_kernel<<<(Bc * Sc * Hc * 32) / 256, 256>>>(gate);

    // flash adds adapter term in epilogue and emits xh/xl split
    flash_mma_kernel<<<dim3(Sc / 128, Hc, Bc), 256, FLASH_SMEM>>>();

    // output projection (weights already transposed into segment 3)
    mma_gemm_kernel<<<dim3(Dc / 128, M / 128), 256, GEMM_SMEM>>>(
        xh, xl, wth + (size_t)3 * Dc * Dc, wtl + (size_t)3 * Dc * Dc,
        fcos, fsin, nullptr, nullptr, nullptr, nullptr, nullptr, nullptr,
        out, 1, Dc);
}

// round 17
// speedup vs baseline: 1.0045x; 1.0012x over previous
#include <cuda_runtime.h>
#include <cuda_bf16.h>
#include <math.h>
#include <stdint.h>

#define Bc 2
#define Sc 2048
#define Dc 2048
#define Hc 16
#define HDc 128
#define Lc 10

// Scratch (static device globals — allocation-free per harness rules)
__device__ float g_attn[Bc*Sc*Dc];
__device__ float g_ak[Lc*Dc];
__device__ float g_av[Lc*Dc];
__device__ float g_partial[2*32*Lc*Dc];
// bf16 split scratch
__device__ __nv_bfloat16 g_xh[Bc*Sc*Dc];   // x split; later attn split
__device__ __nv_bfloat16 g_xl[Bc*Sc*Dc];
__device__ __nv_bfloat16 g_wth[4*Dc*Dc];   // stacked W^T hi [wq|wk|wv|wo]
__device__ __nv_bfloat16 g_wtl[4*Dc*Dc];   // stacked W^T lo
__device__ __nv_bfloat16 g_qh[Bc*Sc*Dc];
__device__ __nv_bfloat16 g_ql[Bc*Sc*Dc];
__device__ __nv_bfloat16 g_kh[Bc*Sc*Dc];
__device__ __nv_bfloat16 g_kl[Bc*Sc*Dc];
__device__ __nv_bfloat16 g_vh[Bc*Sc*Dc];   // [B,S,H,HD] (same layout as K)
__device__ __nv_bfloat16 g_vl[Bc*Sc*Dc];

#define SCALE 0.08838834764831845f  // 1/sqrt(128)

// ---------------------------------------------------------------------------
// mma.sync + ldmatrix + cp.async helpers
// ---------------------------------------------------------------------------
#define MMA16816(c, a0, a1, a2, a3, b0, b1) \
    asm volatile( \
        "mma.sync.aligned.m16n8k16.row.col.f32.bf16.bf16.f32 " \
        "{%0,%1,%2,%3}, {%4,%5,%6,%7}, {%8,%9}, {%0,%1,%2,%3};" \
        : "+f"((c)[0]), "+f"((c)[1]), "+f"((c)[2]), "+f"((c)[3]) \
        : "r"(a0), "r"(a1), "r"(a2), "r"(a3), "r"(b0), "r"(b1))

#define LDSM4(r0, r1, r2, r3, addr) \
    asm volatile("ldmatrix.sync.aligned.m8n8.x4.shared.b16 {%0,%1,%2,%3}, [%4];" \
                 : "=r"(r0), "=r"(r1), "=r"(r2), "=r"(r3) : "r"(addr))

#define LDSM4T(r0, r1, r2, r3, addr) \
    asm volatile("ldmatrix.sync.aligned.m8n8.x4.trans.shared.b16 {%0,%1,%2,%3}, [%4];" \
                 : "=r"(r0), "=r"(r1), "=r"(r2), "=r"(r3) : "r"(addr))

__device__ __forceinline__ uint32_t smem_u32(const void* p) {
    uint32_t a;
    asm("{ .reg .u64 t; cvta.to.shared.u64 t, %1; cvt.u32.u64 %0, t; }"
        : "=r"(a) : "l"(p));
    return a;
}
#define CPA16(saddr, gptr) \
    asm volatile("cp.async.cg.shared.global [%0], [%1], 16;" \
                 :: "r"(saddr), "l"(gptr))
#define CPA_COMMIT() asm volatile("cp.async.commit_group;")
#define CPA_WAIT(n)  asm volatile("cp.async.wait_group %0;" :: "n"(n))

__device__ __forceinline__ __nv_bfloat162 bsplit_hi(float a, float b) {
    __nv_bfloat162 r;
    r.x = __float2bfloat16(a);
    r.y = __float2bfloat16(b);
    return r;
}
__device__ __forceinline__ __nv_bfloat162 bsplit_lo(float a, float b,
                                                    __nv_bfloat162 h) {
    __nv_bfloat162 r;
    r.x = __float2bfloat16(a - __bfloat162float(h.x));
    r.y = __float2bfloat16(b - __bfloat162float(h.y));
    return r;
}

// ---------------------------------------------------------------------------
// Elementwise fp32 -> bf16 hi/lo split (x only); 8 elems per thread.
// ---------------------------------------------------------------------------
__global__ __launch_bounds__(256) void split_kernel(
    const float* __restrict__ x, __nv_bfloat16* __restrict__ h,
    __nv_bfloat16* __restrict__ l)
{
    int i = (blockIdx.x * 256 + threadIdx.x) * 2;
    float4 v0 = ((const float4*)x)[i];
    float4 v1 = ((const float4*)x)[i + 1];
    __nv_bfloat162 h01 = bsplit_hi(v0.x, v0.y);
    __nv_bfloat162 h23 = bsplit_hi(v0.z, v0.w);
    __nv_bfloat162 h45 = bsplit_hi(v1.x, v1.y);
    __nv_bfloat162 h67 = bsplit_hi(v1.z, v1.w);
    ((__nv_bfloat162*)h)[i * 2 + 0] = h01;
    ((__nv_bfloat162*)h)[i * 2 + 1] = h23;
    ((__nv_bfloat162*)h)[i * 2 + 2] = h45;
    ((__nv_bfloat162*)h)[i * 2 + 3] = h67;
    ((__nv_bfloat162*)l)[i * 2 + 0] = bsplit_lo(v0.x, v0.y, h01);
    ((__nv_bfloat162*)l)[i * 2 + 1] = bsplit_lo(v0.z, v0.w, h23);
    ((__nv_bfloat162*)l)[i * 2 + 2] = bsplit_lo(v1.x, v1.y, h45);
    ((__nv_bfloat162*)l)[i * 2 + 3] = bsplit_lo(v1.z, v1.w, h67);
}

// ---------------------------------------------------------------------------
// Transpose + split, 4 weights in one launch (blockIdx.z selects).
// ---------------------------------------------------------------------------
__global__ __launch_bounds__(256) void wtrans4_kernel(
    const float* __restrict__ W0, const float* __restrict__ W1,
    const float* __restrict__ W2, const float* __restrict__ W3,
    __nv_bfloat16* __restrict__ Th, __nv_bfloat16* __restrict__ Tl)
{
    __shared__ float tile[64][33];
    const int z = blockIdx.z;
    const float* W = (z == 0) ? W0 : (z == 1) ? W1 : (z == 2) ? W2 : W3;
    __nv_bfloat16* Tho = Th + (size_t)z * Dc * Dc;
    __nv_bfloat16* Tlo = Tl + (size_t)z * Dc * Dc;
    const int k0 = blockIdx.x * 64, n0 = blockIdx.y * 32;
    const int t = threadIdx.x;
    const int r = t >> 5, c = t & 31;
    #pragma unroll
    for (int i = 0; i < 8; i++)
        tile[r + i * 8][c] = W[(size_t)(k0 + r + i * 8) * Dc + n0 + c];
    __syncthreads();
    #pragma unroll
    for (int i = 0; i < 4; i++) {
        int n = r * 4 + i;
        float v0 = tile[2 * c][n];
        float v1 = tile[2 * c + 1][n];
        __nv_bfloat162 hh = bsplit_hi(v0, v1);
        size_t o = ((size_t)(n0 + n) * Dc + k0) >> 1;
        ((__nv_bfloat162*)Tho)[o + c] = hh;
        ((__nv_bfloat162*)Tlo)[o + c] = bsplit_lo(v0, v1, hh);
    }
}

// ---------------------------------------------------------------------------
// bf16x3 tensor-core GEMM, BK=64, 2-stage cp.async + ldmatrix.  (R14 config)
// ---------------------------------------------------------------------------
#define SROW2 72
#define STG2 36864                         // elems per stage (4 * 128 * 72)
#define GEMM_SMEM (2 * STG2 * 2)           // 147456 bytes

__global__ __launch_bounds__(256, 1) void mma_gemm_kernel(
    const __nv_bfloat16* __restrict__ Ah, const __nv_bfloat16* __restrict__ Al,
    const __nv_bfloat16* __restrict__ BhT, const __nv_bfloat16* __restrict__ BlT,
    const float* __restrict__ fc, const float* __restrict__ fs,
    __nv_bfloat16* __restrict__ oQh, __nv_bfloat16* __restrict__ oQl,
    __nv_bfloat16* __restrict__ oKh, __nv_bfloat16* __restrict__ oKl,
    __nv_bfloat16* __restrict__ oVh, __nv_bfloat16* __restrict__ oVl,
    float* __restrict__ oC, int mode, int K)
{
    extern __shared__ __align__(16) __nv_bfloat16 dsm[];
    const uint32_t sb = smem_u32(dsm);

    const int t = threadIdx.x, lane = t & 31, wid = t >> 5;
    const int wm = wid & 1, wn = wid >> 1;
    const int bm = blockIdx.y * 128, bn = blockIdx.x * 128;
    const int gid = lane >> 2, tig = lane & 3;

    const int aoffE = (wm * 64 + (lane & 15)) * SROW2 + ((lane >> 4) & 1) * 8;
    const int boffE = (wn * 32 + ((lane >> 4) & 1) * 8 + (lane & 7)) * SROW2
                    + ((lane >> 3) & 1) * 8;

    float acc[4][4][4];
    #pragma unroll
    for (int a = 0; a < 4; a++)
        #pragma unroll
        for (int b = 0; b < 4; b++)
            #pragma unroll
            for (int cc = 0; cc < 4; cc++) acc[a][b][cc] = 0.f;

    const int nst = K >> 6;

    #define LOAD_STAGE2(stg, k0) do {                                       \
        uint32_t base = sb + (stg) * STG2 * 2;                              \
        _Pragma("unroll")                                                   \
        for (int jj = 0; jj < 4; jj++) {                                    \
            int u = t + jj * 256;                                           \
            int row = u >> 3, ch = (u & 7) * 8;                             \
            size_t ga = (size_t)(bm + row) * K + (k0) + ch;                 \
            size_t gb = (size_t)(bn + row) * K + (k0) + ch;                 \
            CPA16(base + (row * SROW2 + ch) * 2, &Ah[ga]);                  \
            CPA16(base + (9216 + row * SROW2 + ch) * 2, &Al[ga]);           \
            CPA16(base + (18432 + row * SROW2 + ch) * 2, &BhT[gb]);         \
            CPA16(base + (27648 + row * SROW2 + ch) * 2, &BlT[gb]);         \
        }                                                                   \
        CPA_COMMIT();                                                       \
    } while (0)

    LOAD_STAGE2(0, 0);
    LOAD_STAGE2(1, 64);

    for (int it = 0; it < nst; it++) {
        if (it == nst - 1) { CPA_WAIT(0); } else { CPA_WAIT(1); }
        __syncthreads();

        const uint32_t base = sb + (it & 1) * STG2 * 2;

        #pragma unroll
        for (int ks = 0; ks < 4; ks++) {
            uint32_t ah[4][4], al[4][4];
            #pragma unroll
            for (int mt = 0; mt < 4; mt++) {
                uint32_t aaddr = base + (aoffE + mt * 16 * SROW2 + ks * 16) * 2;
                LDSM4(ah[mt][0], ah[mt][1], ah[mt][2], ah[mt][3], aaddr);
                LDSM4(al[mt][0], al[mt][1], al[mt][2], al[mt][3],
                      aaddr + 9216 * 2);
            }
            #pragma unroll
            for (int ntp = 0; ntp < 2; ntp++) {
                uint32_t baddr = base +
                    (18432 + boffE + ntp * 16 * SROW2 + ks * 16) * 2;
                uint32_t bh0, bh1, bh2, bh3, bl0, bl1, bl2, bl3;
                LDSM4(bh0, bh1, bh2, bh3, baddr);
                LDSM4(bl0, bl1, bl2, bl3, baddr + 9216 * 2);
                #pragma unroll
                for (int mt = 0; mt < 4; mt++) {
                    MMA16816(acc[mt][2 * ntp],     ah[mt][0], ah[mt][1], ah[mt][2], ah[mt][3], bh0, bh1);
                    MMA16816(acc[mt][2 * ntp + 1], ah[mt][0], ah[mt][1], ah[mt][2], ah[mt][3], bh2, bh3);
                    MMA16816(acc[mt][2 * ntp],     ah[mt][0], ah[mt][1], ah[mt][2], ah[mt][3], bl0, bl1);
                    MMA16816(acc[mt][2 * ntp + 1], ah[mt][0], ah[mt][1], ah[mt][2], ah[mt][3], bl2, bl3);
                    MMA16816(acc[mt][2 * ntp],     al[mt][0], al[mt][1], al[mt][2], al[mt][3], bh0, bh1);
                    MMA16816(acc[mt][2 * ntp + 1], al[mt][0], al[mt][1], al[mt][2], al[mt][3], bh2, bh3);
                }
            }
        }
        __syncthreads();
        if (it + 2 < nst) {
            LOAD_STAGE2((it + 2) & 1, (it + 2) * 64);
        }
    }

    // ---- epilogue ----
    #pragma unroll
    for (int mt = 0; mt < 4; mt++) {
        int row = bm + wm * 64 + mt * 16 + gid;
        #pragma unroll
        for (int nt = 0; nt < 4; nt++) {
            int colg = bn + wn * 32 + nt * 8 + tig * 2;
            float a0 = acc[mt][nt][0], a1 = acc[mt][nt][1];
            float a2 = acc[mt][nt][2], a3 = acc[mt][nt][3];
            if (mode == 1) {
                *(float2*)&oC[(size_t)row * Dc + colg] = make_float2(a0, a1);
                *(float2*)&oC[(size_t)(row + 8) * Dc + colg] = make_float2(a2, a3);
            } else {
                int seg = colg >> 11;
                int d = colg & 2047;
                float r00 = a0, r01 = a1, r10 = a2, r11 = a3;
                if (seg < 2) {   // RoPE for Q and K
                    int s0 = row & 2047, s1 = (row + 8) & 2047;
                    int j = (d & 127) >> 1;
                    float c0 = fc[s0 * 64 + j], n0 = fs[s0 * 64 + j];
                    float c1 = fc[s1 * 64 + j], n1 = fs[s1 * 64 + j];
                    r00 = a0 * c0 - a1 * n0; r01 = a0 * n0 + a1 * c0;
                    r10 = a2 * c1 - a3 * n1; r11 = a2 * n1 + a3 * c1;
                }
                __nv_bfloat16* dH = (seg == 0) ? oQh : (seg == 1) ? oKh : oVh;
                __nv_bfloat16* dL = (seg == 0) ? oQl : (seg == 1) ? oKl : oVl;
                size_t o0 = ((size_t)row * Dc + d) >> 1;
                size_t o1 = ((size_t)(row + 8) * Dc + d) >> 1;
                __nv_bfloat162 h0 = bsplit_hi(r00, r01);
                __nv_bfloat162 h1 = bsplit_hi(r10, r11);
                ((__nv_bfloat162*)dH)[o0] = h0;
                ((__nv_bfloat162*)dH)[o1] = h1;
                ((__nv_bfloat162*)dL)[o0] = bsplit_lo(r00, r01, h0);
                ((__nv_bfloat162*)dL)[o1] = bsplit_lo(r10, r11, h1);
            }
        }
    }
}

// ---------------------------------------------------------------------------
// Flash attention (bf16x3), ldmatrix (+trans for V), 2-stage K/V pipeline.
// ---------------------------------------------------------------------------
#define FQS 136
#define FQ_ELEMS (2 * 128 * FQS)              // Qh+Ql
#define FKV_ELEMS (4 * 64 * FQS)              // Kh,Kl,Vh,Vl each 64x136
#define FLASH_SMEM ((FQ_ELEMS + 2 * FKV_ELEMS) * 2)   // 208896 bytes

__global__ __launch_bounds__(256, 1) void flash_mma_kernel()
{
    extern __shared__ __align__(16) __nv_bfloat16 fsm[];
    __nv_bfloat16* sQh = fsm;
    __nv_bfloat16* sQl = sQh + 128 * FQS;
    const uint32_t uQh = smem_u32(sQh), uQl = smem_u32(sQl);
    const uint32_t uS0 = uQh + FQ_ELEMS * 2;

    const int t = threadIdx.x, lane = t & 31, w = t >> 5;
    const int gid = lane >> 2, tig = lane & 3;
    const int qt = gridDim.x - 1 - blockIdx.x;   // longest first
    const int h = blockIdx.y, b = blockIdx.z;
    const int qbase = qt * 128;

    const int qaoffE = (w * 16 + (lane & 15)) * FQS + ((lane >> 4) & 1) * 8;
    const int kboffE = (((lane >> 4) & 1) * 8 + (lane & 7)) * FQS
                     + ((lane >> 3) & 1) * 8;
    const int vboffE = (lane & 15) * FQS + ((lane >> 4) & 1) * 8;

    #pragma unroll
    for (int i = 0; i < 8; i++) {
        int u = t + i * 256;
        int row = u >> 4, c8 = (u & 15) * 8;
        size_t g = ((size_t)(b * Sc + qbase + row)) * Dc + h * HDc + c8;
        *(uint4*)&sQh[row * FQS + c8] = *(const uint4*)&g_qh[g];
        *(uint4*)&sQl[row * FQS + c8] = *(const uint4*)&g_ql[g];
    }

    const int row0 = qbase + w * 16 + gid;
    const int row1 = row0 + 8;

    float m0 = -1e30f, m1 = -1e30f, l0 = 0.f, l1 = 0.f;
    float oacc[16][4];
    #pragma unroll
    for (int i = 0; i < 16; i++)
        #pragma unroll
        for (int j = 0; j < 4; j++) oacc[i][j] = 0.f;

    const int ntk = 2 * qt + 2;

    #define LOAD_KV(kt_) do {                                               \
        const uint32_t sb2 = uS0 + ((kt_) & 1) * FKV_ELEMS * 2;             \
        const int kb_ = (kt_) * 64;                                         \
        _Pragma("unroll")                                                   \
        for (int i = 0; i < 4; i++) {                                       \
            int u = t + i * 256;                                            \
            int krow = u >> 4, c8 = (u & 15) * 8;                           \
            size_t gk = ((size_t)(b * Sc + kb_ + krow)) * Dc + h * HDc + c8;\
            CPA16(sb2 + (krow * FQS + c8) * 2, &g_kh[gk]);                  \
            CPA16(sb2 + (8704 + krow * FQS + c8) * 2, &g_kl[gk]);           \
            CPA16(sb2 + (17408 + krow * FQS + c8) * 2, &g_vh[gk]);          \
            CPA16(sb2 + (26112 + krow * FQS + c8) * 2, &g_vl[gk]);          \
        }                                                                   \
        CPA_COMMIT();                                                       \
    } while (0)

    LOAD_KV(0);

    for (int kt = 0; kt < ntk; kt++) {
        const int kbase = kt * 64;
        if (kt + 1 < ntk) {
            LOAD_KV(kt + 1);
            CPA_WAIT(1);
        } else {
            CPA_WAIT(0);
        }
        __syncthreads();

        const uint32_t sb2 = uS0 + (kt & 1) * FKV_ELEMS * 2;
        const uint32_t uKh2 = sb2, uKl2 = sb2 + 8704 * 2;
        const uint32_t uVh2 = sb2 + 17408 * 2, uVl2 = sb2 + 26112 * 2;

        float sacc[8][4];
        #pragma unroll
        for (int nt = 0; nt < 8; nt++)
            #pragma unroll
            for (int j = 0; j < 4; j++) sacc[nt][j] = 0.f;

        #pragma unroll
        for (int kc = 0; kc < 8; kc++) {
            uint32_t ah0, ah1, ah2, ah3, al0, al1, al2, al3;
            LDSM4(ah0, ah1, ah2, ah3, uQh + (qaoffE + kc * 16) * 2);
            LDSM4(al0, al1, al2, al3, uQl + (qaoffE + kc * 16) * 2);
            #pragma unroll
            for (int ntp = 0; ntp < 4; ntp++) {
                uint32_t kaddr = (kboffE + ntp * 16 * FQS + kc * 16) * 2;
                uint32_t bh0, bh1, bh2, bh3, bl0, bl1, bl2, bl3;
                LDSM4(bh0, bh1, bh2, bh3, uKh2 + kaddr);
                LDSM4(bl0, bl1, bl2, bl3, uKl2 + kaddr);
                MMA16816(sacc[2 * ntp],     ah0, ah1, ah2, ah3, bh0, bh1);
                MMA16816(sacc[2 * ntp + 1], ah0, ah1, ah2, ah3, bh2, bh3);
                MMA16816(sacc[2 * ntp],     ah0, ah1, ah2, ah3, bl0, bl1);
                MMA16816(sacc[2 * ntp + 1], ah0, ah1, ah2, ah3, bl2, bl3);
                MMA16816(sacc[2 * ntp],     al0, al1, al2, al3, bh0, bh1);
                MMA16816(sacc[2 * ntp + 1], al0, al1, al2, al3, bh2, bh3);
            }
        }

        const bool need_mask = (kt >= 2 * qt);
        #pragma unroll
        for (int nt = 0; nt < 8; nt++) {
            int c0 = kbase + nt * 8 + 2 * tig;
            float v0 = sacc[nt][0] * SCALE;
            float v1 = sacc[nt][1] * SCALE;
            float v2 = sacc[nt][2] * SCALE;
            float v3 = sacc[nt][3] * SCALE;
            if (need_mask) {
                if (c0 > row0)     v0 -= 1e9f;
                if (c0 + 1 > row0) v1 -= 1e9f;
                if (c0 > row1)     v2 -= 1e9f;
                if (c0 + 1 > row1) v3 -= 1e9f;
            }
            sacc[nt][0] = v0; sacc[nt][1] = v1;
            sacc[nt][2] = v2; sacc[nt][3] = v3;
        }

        float mx0 = -1e30f, mx1 = -1e30f;
        #pragma unroll
        for (int nt = 0; nt < 8; nt++) {
            mx0 = fmaxf(mx0, fmaxf(sacc[nt][0], sacc[nt][1]));
            mx1 = fmaxf(mx1, fmaxf(sacc[nt][2], sacc[nt][3]));
        }
        mx0 = fmaxf(mx0, __shfl_xor_sync(0xffffffffu, mx0, 1));
        mx0 = fmaxf(mx0, __shfl_xor_sync(0xffffffffu, mx0, 2));
        mx1 = fmaxf(mx1, __shfl_xor_sync(0xffffffffu, mx1, 1));
        mx1 = fmaxf(mx1, __shfl_xor_sync(0xffffffffu, mx1, 2));
        float nm0 = fmaxf(m0, mx0), nm1 = fmaxf(m1, mx1);
        float corr0 = __expf(m0 - nm0), corr1 = __expf(m1 - nm1);
        m0 = nm0; m1 = nm1;

        float rs0 = 0.f, rs1 = 0.f;
        uint32_t ph01[8], ph23[8], pl01[8], pl23[8];
        #pragma unroll
        for (int nt = 0; nt < 8; nt++) {
            float e0 = __expf(sacc[nt][0] - nm0);
            float e1 = __expf(sacc[nt][1] - nm0);
            float e2 = __expf(sacc[nt][2] - nm1);
            float e3 = __expf(sacc[nt][3] - nm1);
            rs0 += e0 + e1; rs1 += e2 + e3;
            __nv_bfloat162 h01 = __floats2bfloat162_rn(e0, e1);
            __nv_bfloat162 h23 = __floats2bfloat162_rn(e2, e3);
            __nv_bfloat162 lo01 = __floats2bfloat162_rn(
                e0 - __bfloat162float(h01.x), e1 - __bfloat162float(h01.y));
            __nv_bfloat162 lo23 = __floats2bfloat162_rn(
                e2 - __bfloat162float(h23.x), e3 - __bfloat162float(h23.y));
            ph01[nt] = *(uint32_t*)&h01;
            ph23[nt] = *(uint32_t*)&h23;
            pl01[nt] = *(uint32_t*)&lo01;
            pl23[nt] = *(uint32_t*)&lo23;
        }
        rs0 += __shfl_xor_sync(0xffffffffu, rs0, 1);
        rs0 += __shfl_xor_sync(0xffffffffu, rs0, 2);
        rs1 += __shfl_xor_sync(0xffffffffu, rs1, 1);
        rs1 += __shfl_xor_sync(0xffffffffu, rs1, 2);
        l0 = l0 * corr0 + rs0;
        l1 = l1 * corr1 + rs1;

        #pragma unroll
        for (int nto = 0; nto < 16; nto++) {
            oacc[nto][0] *= corr0; oacc[nto][1] *= corr0;
            oacc[nto][2] *= corr1; oacc[nto][3] *= corr1;
        }

        // ---- O += P V (V fragments via ldmatrix.trans from [s][d]) ----
        #pragma unroll
        for (int j = 0; j < 4; j++) {
            uint32_t a0h = ph01[2 * j],     a1h = ph23[2 * j];
            uint32_t a2h = ph01[2 * j + 1], a3h = ph23[2 * j + 1];
            uint32_t a0l = pl01[2 * j],     a1l = pl23[2 * j];
            uint32_t a2l = pl01[2 * j + 1], a3l = pl23[2 * j + 1];
            #pragma unroll
            for (int ntp = 0; ntp < 4; ntp++) {
                uint32_t vaddr = (vboffE + j * 16 * FQS + ntp * 32) * 2;
                uint32_t vh0, vh1, vh2, vh3, vl0, vl1, vl2, vl3;
                LDSM4T(vh0, vh1, vh2, vh3, uVh2 + vaddr);
                LDSM4T(vl0, vl1, vl2, vl3, uVl2 + vaddr);
                MMA16816(oacc[4 * ntp],     a0h, a1h, a2h, a3h, vh0, vh1);
                MMA16816(oacc[4 * ntp + 1], a0h, a1h, a2h, a3h, vh2, vh3);
                MMA16816(oacc[4 * ntp],     a0h, a1h, a2h, a3h, vl0, vl1);
                MMA16816(oacc[4 * ntp + 1], a0h, a1h, a2h, a3h, vl2, vl3);
                MMA16816(oacc[4 * ntp],     a0l, a1l, a2l, a3l, vh0, vh1);
                MMA16816(oacc[4 * ntp + 1], a0l, a1l, a2l, a3l, vh2, vh3);

                uint32_t vaddr2 = (vboffE + j * 16 * FQS + ntp * 32 + 16) * 2;
                uint32_t wh0, wh1, wh2, wh3, wl0, wl1, wl2, wl3;
                LDSM4T(wh0, wh1, wh2, wh3, uVh2 + vaddr2);
                LDSM4T(wl0, wl1, wl2, wl3, uVl2 + vaddr2);
                MMA16816(oacc[4 * ntp + 2], a0h, a1h, a2h, a3h, wh0, wh1);
                MMA16816(oacc[4 * ntp + 3], a0h, a1h, a2h, a3h, wh2, wh3);
                MMA16816(oacc[4 * ntp + 2], a0h, a1h, a2h, a3h, wl0, wl1);
                MMA16816(oacc[4 * ntp + 3], a0h, a1h, a2h, a3h, wl2, wl3);
                MMA16816(oacc[4 * ntp + 2], a0l, a1l, a2l, a3l, wh0, wh1);
                MMA16816(oacc[4 * ntp + 3], a0l, a1l, a2l, a3l, wh2, wh3);
            }
        }
        __syncthreads();
    }

    // ---- epilogue: add adapter contribution, emit bf16 hi/lo split ----
    float i0 = 1.f / l0, i1 = 1.f / l1;
    #pragma unroll
    for (int nto = 0; nto < 16; nto++) {
        int col = h * HDc + nto * 8 + 2 * tig;
        size_t o0 = ((size_t)(b * Sc + row0)) * Dc + col;
        size_t o1 = ((size_t)(b * Sc + row1)) * Dc + col;
        float2 ad0 = *(const float2*)&g_attn[o0];
        float2 ad1 = *(const float2*)&g_attn[o1];
        float f00 = oacc[nto][0] * i0 + ad0.x;
        float f01 = oacc[nto][1] * i0 + ad0.y;
        float f10 = oacc[nto][2] * i1 + ad1.x;
        float f11 = oacc[nto][3] * i1 + ad1.y;
        __nv_bfloat162 h0 = bsplit_hi(f00, f01);
        __nv_bfloat162 h1 = bsplit_hi(f10, f11);
        ((__nv_bfloat162*)g_xh)[o0 >> 1] = h0;
        ((__nv_bfloat162*)g_xh)[o1 >> 1] = h1;
        ((__nv_bfloat162*)g_xl)[o0 >> 1] = bsplit_lo(f00, f01, h0);
        ((__nv_bfloat162*)g_xl)[o1 >> 1] = bsplit_lo(f10, f11, h1);
    }
}

// ---------------------------------------------------------------------------
// Adapter projection (both weights): grid (Dc/128, 32 k-splits, 2), 128 thr.
// ---------------------------------------------------------------------------
__global__ __launch_bounds__(128) void adapter_proj2_kernel(
    const float* __restrict__ A, const float* __restrict__ Wk,
    const float* __restrict__ Wv, float* __restrict__ P)
{
    __shared__ float sA[Lc][64];
    const int nb = blockIdx.x, ks = blockIdx.y, z = blockIdx.z;
    const float* W = z ? Wv : Wk;
    const int t = threadIdx.x;

    for (int idx = t; idx < Lc * 64; idx += 128) {
        int l = idx >> 6, kk = idx & 63;
        sA[l][kk] = A[l * Dc + ks * 64 + kk];
    }
    __syncthreads();

    const int n = nb * 128 + t;
    float acc[Lc];
    #pragma unroll
    for (int l = 0; l < Lc; l++) acc[l] = 0.f;

    #pragma unroll 8
    for (int kk = 0; kk < 64; kk++) {
        float wv = W[(size_t)(ks * 64 + kk) * Dc + n];
        #pragma unroll
        for (int l = 0; l < Lc; l++)
            acc[l] += sA[l][kk] * wv;
    }

    float* p = &P[((size_t)(z * 32 + ks) * Lc) * Dc + n];
    #pragma unroll
    for (int l = 0; l < Lc; l++)
        p[(size_t)l * Dc] = acc[l];
}

// Fused reduce: float4 per thread, sums 32 k-split partials for both weights.
__global__ __launch_bounds__(256) void adapter_reduce2_kernel(
    const float* __restrict__ P, float* __restrict__ AK,
    float* __restrict__ AV)
{
    int i4 = (blockIdx.x * 256 + threadIdx.x) * 4;   // 0 .. 2*Lc*Dc-1 step 4
    int z = i4 / (Lc * Dc);
    int r = i4 - z * Lc * Dc;                        // l*Dc + n (4-aligned)
    float4 s = make_float4(0.f, 0.f, 0.f, 0.f);
    #pragma unroll
    for (int ks = 0; ks < 32; ks++) {
        float4 v = *(const float4*)&P[((size_t)(z * 32 + ks) * Lc) * Dc + r];
        s.x += v.x; s.y += v.y; s.z += v.z; s.w += v.w;
    }
    float* dst = (z == 0) ? AK : AV;
    *(float4*)&dst[r] = s;
}

// ---------------------------------------------------------------------------
// Adapter attention: one warp per (b,s,h). Writes (not RMW).
// ---------------------------------------------------------------------------
__global__ __launch_bounds__(256) void adapter_attn_kernel(
    const float* __restrict__ gate)
{
    int gw = (blockIdx.x * blockDim.x + threadIdx.x) >> 5;
    int lane = threadIdx.x & 31;
    if (gw >= Bc * Sc * Hc) return;
    int h = gw % Hc;
    int s = (gw / Hc) % Sc;
    int b = gw / (Hc * Sc);

    size_t qoff = ((size_t)(b * Sc + s)) * Dc + h * HDc + lane * 4;
    __nv_bfloat162 qh01 = ((const __nv_bfloat162*)g_qh)[qoff >> 1];
    __nv_bfloat162 qh23 = ((const __nv_bfloat162*)g_qh)[(qoff >> 1) + 1];
    __nv_bfloat162 ql01 = ((const __nv_bfloat162*)g_ql)[qoff >> 1];
    __nv_bfloat162 ql23 = ((const __nv_bfloat162*)g_ql)[(qoff >> 1) + 1];
    float4 q4;
    q4.x = __bfloat162float(qh01.x) + __bfloat162float(ql01.x);
    q4.y = __bfloat162float(qh01.y) + __bfloat162float(ql01.y);
    q4.z = __bfloat162float(qh23.x) + __bfloat162float(ql23.x);
    q4.w = __bfloat162float(qh23.y) + __bfloat162float(ql23.y);

    float scv[Lc];
    #pragma unroll
    for (int l = 0; l < Lc; l++) {
        float4 a4 = *(const float4*)(g_ak + (size_t)l * Dc + h * HDc + lane * 4);
        float p = q4.x * a4.x + q4.y * a4.y + q4.z * a4.z + q4.w * a4.w;
        #pragma unroll
        for (int o = 16; o > 0; o >>= 1)
            p += __shfl_xor_sync(0xffffffffu, p, o);
        scv[l] = p * SCALE;
    }
    float m = scv[0];
    #pragma unroll
    for (int l = 1; l < Lc; l++) m = fmaxf(m, scv[l]);
    float sum = 0.f;
    float e[Lc];
    #pragma unroll
    for (int l = 0; l < Lc; l++) { e[l] = expf(scv[l] - m); sum += e[l]; }
    float g = gate[h] / sum;

    float4 acc = make_float4(0.f, 0.f, 0.f, 0.f);
    #pragma unroll
    for (int l = 0; l < Lc; l++) {
        float4 a4 = *(const float4*)(g_av + (size_t)l * Dc + h * HDc + lane * 4);
        acc.x += e[l] * a4.x;
        acc.y += e[l] * a4.y;
        acc.z += e[l] * a4.z;
        acc.w += e[l] * a4.w;
    }
    float4 o4;
    o4.x = g * acc.x; o4.y = g * acc.y;
    o4.z = g * acc.z; o4.w = g * acc.w;
    *(float4*)(g_attn + qoff) = o4;
}

// ---------------------------------------------------------------------------
extern "C" void kernel_launch(void* const* d_in, const int* in_sizes, int n_in,
                              void* d_out, int out_size)
{
    const float* x       = (const float*)d_in[0];
    const float* wq      = (const float*)d_in[1];
    const float* wk      = (const float*)d_in[2];
    const float* wv      = (const float*)d_in[3];
    const float* wo      = (const float*)d_in[4];
    const float* adapter = (const float*)d_in[5];
    const float* gate    = (const float*)d_in[6];
    const float* fcos    = (const float*)d_in[7];
    const float* fsin    = (const float*)d_in[8];
    float* out = (float*)d_out;

    float *ak, *av, *part;
    __nv_bfloat16 *xh, *xl, *wth, *wtl, *qh, *ql, *kh, *kl, *vh, *vl;
    cudaGetSymbolAddress((void**)&ak,   g_ak);
    cudaGetSymbolAddress((void**)&av,   g_av);
    cudaGetSymbolAddress((void**)&part, g_partial);
    cudaGetSymbolAddress((void**)&xh,   g_xh);
    cudaGetSymbolAddress((void**)&xl,   g_xl);
    cudaGetSymbolAddress((void**)&wth,  g_wth);
    cudaGetSymbolAddress((void**)&wtl,  g_wtl);
    cudaGetSymbolAddress((void**)&qh,   g_qh);
    cudaGetSymbolAddress((void**)&ql,   g_ql);
    cudaGetSymbolAddress((void**)&kh,   g_kh);
    cudaGetSymbolAddress((void**)&kl,   g_kl);
    cudaGetSymbolAddress((void**)&vh,   g_vh);
    cudaGetSymbolAddress((void**)&vl,   g_vl);

    const int M = Bc * Sc;   // 4096

    cudaFuncSetAttribute(mma_gemm_kernel,
                         cudaFuncAttributeMaxDynamicSharedMemorySize,
                         GEMM_SMEM);
    cudaFuncSetAttribute(flash_mma_kernel,
                         cudaFuncAttributeMaxDynamicSharedMemorySize,
                         FLASH_SMEM);

    // persistent side stream + events for graph-capture fork/join
    static cudaStream_t s_side = nullptr;
    static cudaEvent_t e_fork = nullptr, e_wt = nullptr, e_join = nullptr;
    if (s_side == nullptr) {
        cudaStreamCreateWithFlags(&s_side, cudaStreamNonBlocking);
        cudaEventCreateWithFlags(&e_fork, cudaEventDisableTiming);
        cudaEventCreateWithFlags(&e_wt,   cudaEventDisableTiming);
        cudaEventCreateWithFlags(&e_join, cudaEventDisableTiming);
    }

    // fork side stream from the capture (default) stream
    cudaEventRecord(e_fork, 0);
    cudaStreamWaitEvent(s_side, e_fork, 0);

    // main: split x -> bf16 hi/lo (8 elems/thread)
    split_kernel<<<(M * Dc / 8) / 256, 256>>>(x, xh, xl);

    // side: weight transposes, then adapter projections + reduce
    wtrans4_kernel<<<dim3(Dc / 64, Dc / 32, 4), 256, 0, s_side>>>(
        wq, wk, wv, wo, wth, wtl);
    cudaEventRecord(e_wt, s_side);
    adapter_proj2_kernel<<<dim3(Dc / 128, 32, 2), 128, 0, s_side>>>(
        adapter, wk, wv, part);
    adapter_reduce2_kernel<<<(2 * Lc * Dc / 4) / 256, 256, 0, s_side>>>(
        part, ak, av);
    cudaEventRecord(e_join, s_side);

    // main: QKV GEMM needs split (main) + wtrans (side)
    cudaStreamWaitEvent(0, e_wt, 0);
    mma_gemm_kernel<<<dim3(3 * Dc / 128, M / 128), 256, GEMM_SMEM>>>(
        xh, xl, wth, wtl, fcos, fsin, qh, ql, kh, kl, vh, vl, nullptr, 0, Dc);

    // main: adapter attention needs qh/ql (main) + ak/av (side)
    cudaStreamWaitEvent(0, e_join, 0);
    adapter_attn_kernel<<<(Bc * Sc * Hc * 32) / 256, 256>>>(gate);

    // flash adds adapter term in epilogue and emits xh/xl split
    flash_mma_kernel<<<dim3(Sc / 128, Hc, Bc), 256, FLASH_SMEM>>>();

    // output projection (weights already transposed into segment 3)
    mma_gemm_kernel<<<dim3(Dc / 128, M / 128), 256, GEMM_SMEM>>>(
        xh, xl, wth + (size_t)3 * Dc * Dc, wtl + (size_t)3 * Dc * Dc,
        fcos, fsin, nullptr, nullptr, nullptr, nullptr, nullptr, nullptr,
        out, 1, Dc);
}